// round 1
// baseline (speedup 1.0000x reference)
#include <cuda_runtime.h>
#include <math.h>
#include <stdint.h>

#define E_DIM 1024
#define H_DIM 16
#define D_DIM 64
#define S_LEN 1024
#define N_B   4
#define L_NUM 4
#define FF_DIM 4096
#define V_DIM 32000
#define M_TOK (N_B * S_LEN)   // 4096 token rows

// ---------------------------------------------------------------------------
// Scratch (device globals; no allocations allowed)
// ---------------------------------------------------------------------------
__device__ float g_act [M_TOK * E_DIM];
__device__ float g_q   [M_TOK * E_DIM];
__device__ float g_k   [M_TOK * E_DIM];
__device__ float g_v   [M_TOK * E_DIM];
__device__ float g_attn[M_TOK * E_DIM];
__device__ float g_tmp [M_TOK * E_DIM];
__device__ float g_h   [M_TOK * E_DIM];
__device__ float g_ff  [M_TOK * FF_DIM];

// ---------------------------------------------------------------------------
// Embedding + sinusoidal positional encoding
// out[row, e] = emb[x[row], e] + PE(s, e), row = n*S + s
// ---------------------------------------------------------------------------
__global__ void embed_kernel(const int* __restrict__ x,
                             const float* __restrict__ emb,
                             float* __restrict__ out)
{
    int row = blockIdx.x;           // 0..4095
    int s   = row & (S_LEN - 1);    // S = 1024 (power of 2)
    int tok = x[row];
    const float* erow = emb + (size_t)tok * E_DIM;
    float* orow = out + (size_t)row * E_DIM;

    int e0 = threadIdx.x * 4;       // 256 threads * 4 = 1024
    #pragma unroll
    for (int j = 0; j < 4; j++) {
        int e = e0 + j;
        int even = e & ~1;                          // 2*i
        float expo = (float)even / (float)E_DIM;    // even_i / d_model
        float denom = powf(10000.0f, expo);
        float ang = (float)s / denom;
        float pe = (e & 1) ? cosf(ang) : sinf(ang);
        orow[e] = erow[e] + pe;
    }
}

// ---------------------------------------------------------------------------
// SGEMM: C[M,N] = A[M,K] @ B[K,N] + bias[N], optional ReLU.
// 128x128 tile, BK=16, 256 threads, 8x8 per-thread microtile.
// All dims divisible by tile sizes (asserted by problem shapes).
// ---------------------------------------------------------------------------
#define BM 128
#define BN 128
#define BK 16

template<int RELU>
__global__ __launch_bounds__(256)
void sgemm_bias(const float* __restrict__ A, const float* __restrict__ B,
                const float* __restrict__ bias, float* __restrict__ C,
                int Md, int Nd, int Kd)
{
    __shared__ float As[BK * BM];
    __shared__ float Bs[BK * BN];

    int tid = threadIdx.x;
    int m0 = blockIdx.y * BM;
    int n0 = blockIdx.x * BN;
    int tr = tid >> 4;      // 0..15
    int tc = tid & 15;      // 0..15

    float acc[8][8];
    #pragma unroll
    for (int i = 0; i < 8; i++)
        #pragma unroll
        for (int j = 0; j < 8; j++) acc[i][j] = 0.0f;

    for (int k0 = 0; k0 < Kd; k0 += BK) {
        // A tile: 128 rows x 16 k -> store transposed As[k][m]
        #pragma unroll
        for (int l = 0; l < 2; l++) {
            int idx = tid + l * 256;            // 0..511 float4s
            int row = idx >> 2;
            int c4  = idx & 3;
            float4 v = *(const float4*)(A + (size_t)(m0 + row) * Kd + k0 + c4 * 4);
            As[(c4 * 4 + 0) * BM + row] = v.x;
            As[(c4 * 4 + 1) * BM + row] = v.y;
            As[(c4 * 4 + 2) * BM + row] = v.z;
            As[(c4 * 4 + 3) * BM + row] = v.w;
        }
        // B tile: 16 k x 128 n, row-major copy
        #pragma unroll
        for (int l = 0; l < 2; l++) {
            int idx = tid + l * 256;
            int r  = idx >> 5;
            int c4 = idx & 31;
            *(float4*)(Bs + r * BN + c4 * 4) =
                *(const float4*)(B + (size_t)(k0 + r) * Nd + n0 + c4 * 4);
        }
        __syncthreads();

        #pragma unroll
        for (int k = 0; k < BK; k++) {
            float a[8], b[8];
            *(float4*)(a + 0) = *(const float4*)(As + k * BM + tr * 8 + 0);
            *(float4*)(a + 4) = *(const float4*)(As + k * BM + tr * 8 + 4);
            *(float4*)(b + 0) = *(const float4*)(Bs + k * BN + tc * 8 + 0);
            *(float4*)(b + 4) = *(const float4*)(Bs + k * BN + tc * 8 + 4);
            #pragma unroll
            for (int i = 0; i < 8; i++)
                #pragma unroll
                for (int j = 0; j < 8; j++)
                    acc[i][j] = fmaf(a[i], b[j], acc[i][j]);
        }
        __syncthreads();
    }

    // Epilogue: bias (+ReLU)
    float bb[8];
    #pragma unroll
    for (int j = 0; j < 8; j++) bb[j] = bias[n0 + tc * 8 + j];

    #pragma unroll
    for (int i = 0; i < 8; i++) {
        int row = m0 + tr * 8 + i;
        float* crow = C + (size_t)row * Nd + n0 + tc * 8;
        #pragma unroll
        for (int j = 0; j < 8; j += 4) {
            float4 o;
            o.x = acc[i][j + 0] + bb[j + 0];
            o.y = acc[i][j + 1] + bb[j + 1];
            o.z = acc[i][j + 2] + bb[j + 2];
            o.w = acc[i][j + 3] + bb[j + 3];
            if (RELU) {
                o.x = fmaxf(o.x, 0.0f); o.y = fmaxf(o.y, 0.0f);
                o.z = fmaxf(o.z, 0.0f); o.w = fmaxf(o.w, 0.0f);
            }
            *(float4*)(crow + j) = o;
        }
    }
}

// ---------------------------------------------------------------------------
// Fused causal attention, one CTA (128 threads) per (n, h, q).
// q/k/v layout: [row = n*S + s, col = h*64 + d]
// scale = 1/sqrt(E) = 1/32  (reference divides by sqrt(embed_size)!)
// ---------------------------------------------------------------------------
__global__ __launch_bounds__(128)
void attn_kernel(const float* __restrict__ Q, const float* __restrict__ K,
                 const float* __restrict__ V, float* __restrict__ O)
{
    __shared__ float sh_q[D_DIM];
    __shared__ float lg[S_LEN];
    __shared__ float sred[128];

    int qi = blockIdx.x;   // query position
    int h  = blockIdx.y;
    int n  = blockIdx.z;
    int tid = threadIdx.x;

    const size_t base = ((size_t)n * S_LEN) * E_DIM + h * D_DIM;
    const float scale = 1.0f / 32.0f;   // 1/sqrt(1024)

    if (tid < D_DIM)
        sh_q[tid] = Q[base + (size_t)qi * E_DIM + tid];
    __syncthreads();

    int nk = qi + 1;   // causal: keys 0..qi

    // logits
    for (int k = tid; k < nk; k += 128) {
        const float* krow = K + base + (size_t)k * E_DIM;
        float dot = 0.0f;
        #pragma unroll
        for (int d4 = 0; d4 < D_DIM; d4 += 4) {
            float4 kv = *(const float4*)(krow + d4);
            float4 qv = *(const float4*)(sh_q + d4);
            dot = fmaf(kv.x, qv.x, dot);
            dot = fmaf(kv.y, qv.y, dot);
            dot = fmaf(kv.z, qv.z, dot);
            dot = fmaf(kv.w, qv.w, dot);
        }
        lg[k] = dot * scale;
    }
    __syncthreads();

    // max
    float lmax = -1e30f;
    for (int k = tid; k < nk; k += 128) lmax = fmaxf(lmax, lg[k]);
    sred[tid] = lmax;
    __syncthreads();
    #pragma unroll
    for (int s = 64; s > 0; s >>= 1) {
        if (tid < s) sred[tid] = fmaxf(sred[tid], sred[tid + s]);
        __syncthreads();
    }
    float mx = sred[0];
    __syncthreads();

    // exp + sum
    float lsum = 0.0f;
    for (int k = tid; k < nk; k += 128) {
        float p = expf(lg[k] - mx);
        lg[k] = p;
        lsum += p;
    }
    sred[tid] = lsum;
    __syncthreads();
    #pragma unroll
    for (int s = 64; s > 0; s >>= 1) {
        if (tid < s) sred[tid] += sred[tid + s];
        __syncthreads();
    }
    float inv = 1.0f / sred[0];
    __syncthreads();

    // PV: threads split as (half = tid/64) x (d = tid%64)
    int d = tid & 63;
    int half = tid >> 6;
    float acc = 0.0f;
    for (int k = half; k < nk; k += 2)
        acc = fmaf(lg[k], V[base + (size_t)k * E_DIM + d], acc);
    sred[tid] = acc;
    __syncthreads();
    if (tid < D_DIM)
        O[base + (size_t)qi * E_DIM + tid] = (sred[tid] + sred[tid + 64]) * inv;
}

// ---------------------------------------------------------------------------
// Residual add + LayerNorm: out = LN(a + b) * g + beta, one CTA per row
// ---------------------------------------------------------------------------
__global__ __launch_bounds__(256)
void add_ln_kernel(const float* __restrict__ a, const float* __restrict__ b,
                   const float* __restrict__ g, const float* __restrict__ beta,
                   float* __restrict__ out)
{
    __shared__ float sred[256];
    int row = blockIdx.x;
    int tid = threadIdx.x;
    const float* ar = a + (size_t)row * E_DIM;
    const float* br = b + (size_t)row * E_DIM;
    float* orow = out + (size_t)row * E_DIM;

    float xv[4];
    float lsum = 0.0f;
    #pragma unroll
    for (int j = 0; j < 4; j++) {
        int e = tid + j * 256;
        xv[j] = ar[e] + br[e];
        lsum += xv[j];
    }
    sred[tid] = lsum;
    __syncthreads();
    #pragma unroll
    for (int s = 128; s > 0; s >>= 1) {
        if (tid < s) sred[tid] += sred[tid + s];
        __syncthreads();
    }
    float mean = sred[0] * (1.0f / E_DIM);
    __syncthreads();

    float lvar = 0.0f;
    #pragma unroll
    for (int j = 0; j < 4; j++) {
        float d = xv[j] - mean;
        lvar += d * d;
    }
    sred[tid] = lvar;
    __syncthreads();
    #pragma unroll
    for (int s = 128; s > 0; s >>= 1) {
        if (tid < s) sred[tid] += sred[tid + s];
        __syncthreads();
    }
    float rstd = rsqrtf(sred[0] * (1.0f / E_DIM) + 1e-5f);

    #pragma unroll
    for (int j = 0; j < 4; j++) {
        int e = tid + j * 256;
        orow[e] = (xv[j] - mean) * rstd * g[e] + beta[e];
    }
}

// ---------------------------------------------------------------------------
// Launch
// ---------------------------------------------------------------------------
extern "C" void kernel_launch(void* const* d_in, const int* in_sizes, int n_in,
                              void* d_out, int out_size)
{
    const int*   x    = (const int*)  d_in[0];
    const float* emb  = (const float*)d_in[1];
    const float* Wq   = (const float*)d_in[2];
    const float* bq   = (const float*)d_in[3];
    const float* Wk   = (const float*)d_in[4];
    const float* bk   = (const float*)d_in[5];
    const float* Wv   = (const float*)d_in[6];
    const float* bv   = (const float*)d_in[7];
    const float* Wo   = (const float*)d_in[8];
    const float* bo   = (const float*)d_in[9];
    const float* ln1g = (const float*)d_in[10];
    const float* ln1b = (const float*)d_in[11];
    const float* ln2g = (const float*)d_in[12];
    const float* ln2b = (const float*)d_in[13];
    const float* W1   = (const float*)d_in[14];
    const float* b1   = (const float*)d_in[15];
    const float* W2   = (const float*)d_in[16];
    const float* b2   = (const float*)d_in[17];
    const float* Wout = (const float*)d_in[18];
    const float* bout = (const float*)d_in[19];
    float* out = (float*)d_out;

    float *act, *q, *k, *v, *attn, *tmp, *hbuf, *ff;
    cudaGetSymbolAddress((void**)&act,  g_act);
    cudaGetSymbolAddress((void**)&q,    g_q);
    cudaGetSymbolAddress((void**)&k,    g_k);
    cudaGetSymbolAddress((void**)&v,    g_v);
    cudaGetSymbolAddress((void**)&attn, g_attn);
    cudaGetSymbolAddress((void**)&tmp,  g_tmp);
    cudaGetSymbolAddress((void**)&hbuf, g_h);
    cudaGetSymbolAddress((void**)&ff,   g_ff);

    embed_kernel<<<M_TOK, 256>>>(x, emb, act);

    dim3 gE (E_DIM  / BN, M_TOK / BM);   // N=1024
    dim3 gFF(FF_DIM / BN, M_TOK / BM);   // N=4096
    dim3 gV (V_DIM  / BN, M_TOK / BM);   // N=32000

    for (int i = 0; i < L_NUM; i++) {
        size_t wo = (size_t)i * E_DIM * E_DIM;
        size_t bo_off = (size_t)i * E_DIM;

        sgemm_bias<0><<<gE, 256>>>(act, Wq + wo, bq + bo_off, q,    M_TOK, E_DIM, E_DIM);
        sgemm_bias<0><<<gE, 256>>>(act, Wk + wo, bk + bo_off, k,    M_TOK, E_DIM, E_DIM);
        sgemm_bias<0><<<gE, 256>>>(act, Wv + wo, bv + bo_off, v,    M_TOK, E_DIM, E_DIM);

        attn_kernel<<<dim3(S_LEN, H_DIM, N_B), 128>>>(q, k, v, attn);

        sgemm_bias<0><<<gE, 256>>>(attn, Wo + wo, bo + bo_off, tmp, M_TOK, E_DIM, E_DIM);

        add_ln_kernel<<<M_TOK, 256>>>(tmp, act, ln1g + bo_off, ln1b + bo_off, hbuf);

        sgemm_bias<1><<<gFF, 256>>>(hbuf, W1 + (size_t)i * E_DIM * FF_DIM,
                                    b1 + (size_t)i * FF_DIM, ff, M_TOK, FF_DIM, E_DIM);
        sgemm_bias<0><<<gE, 256>>>(ff, W2 + (size_t)i * FF_DIM * E_DIM,
                                   b2 + bo_off, tmp, M_TOK, E_DIM, FF_DIM);

        add_ln_kernel<<<M_TOK, 256>>>(tmp, hbuf, ln2g + bo_off, ln2b + bo_off, act);
    }

    sgemm_bias<0><<<gV, 256>>>(act, Wout, bout, out, M_TOK, V_DIM, E_DIM);
}

// round 2
// speedup vs baseline: 1.7530x; 1.7530x over previous
#include <cuda_runtime.h>
#include <math.h>
#include <stdint.h>

#define E_DIM 1024
#define H_DIM 16
#define D_DIM 64
#define S_LEN 1024
#define N_B   4
#define L_NUM 4
#define FF_DIM 4096
#define V_DIM 32000
#define M_TOK (N_B * S_LEN)   // 4096 token rows

// ---------------------------------------------------------------------------
// Scratch (device globals; no allocations allowed)
// ---------------------------------------------------------------------------
__device__ float g_act [M_TOK * E_DIM];
__device__ float g_q   [M_TOK * E_DIM];
__device__ float g_k   [M_TOK * E_DIM];
__device__ float g_v   [M_TOK * E_DIM];
__device__ float g_attn[M_TOK * E_DIM];
__device__ float g_tmp [M_TOK * E_DIM];
__device__ float g_h   [M_TOK * E_DIM];
__device__ float g_ff  [M_TOK * FF_DIM];

// ---------------------------------------------------------------------------
// Embedding + sinusoidal positional encoding
// ---------------------------------------------------------------------------
__global__ void embed_kernel(const int* __restrict__ x,
                             const float* __restrict__ emb,
                             float* __restrict__ out)
{
    int row = blockIdx.x;
    int s   = row & (S_LEN - 1);
    int tok = x[row];
    const float* erow = emb + (size_t)tok * E_DIM;
    float* orow = out + (size_t)row * E_DIM;

    int e0 = threadIdx.x * 4;
    #pragma unroll
    for (int j = 0; j < 4; j++) {
        int e = e0 + j;
        int even = e & ~1;
        float expo = (float)even / (float)E_DIM;
        float denom = powf(10000.0f, expo);
        float ang = (float)s / denom;
        float pe = (e & 1) ? cosf(ang) : sinf(ang);
        orow[e] = erow[e] + pe;
    }
}

// ---------------------------------------------------------------------------
// TF32 tensor-core GEMM: C[M,N] = A[M,K] @ B[K,N] + bias, optional ReLU
// 128x128 CTA tile, BK=16, 256 threads (8 warps, 2x4), warp tile 64x32.
// mma.m16n8k8 tf32. Double-buffered SMEM via cp.async.
// SMEM strides padded for conflict-free fragment loads:
//   A: [128][20]  (bank = (m*20+k)%32 covers all 32 banks per warp)
//   B: [16][136]  (bank = (k*136+n)%32 = (k*8+n)%32 covers all 32)
// ---------------------------------------------------------------------------
#define BM 128
#define BN 128
#define BK 16
#define ASTRIDE 20
#define BSTRIDE 136

__device__ __forceinline__ uint32_t f2tf32(float x) {
    uint32_t r;
    asm("cvt.rna.tf32.f32 %0, %1;" : "=r"(r) : "f"(x));
    return r;
}

template<int RELU>
__global__ __launch_bounds__(256)
void tgemm_bias(const float* __restrict__ A, const float* __restrict__ B,
                const float* __restrict__ bias, float* __restrict__ C,
                int Md, int Nd, int Kd)
{
    __shared__ float As[2][BM * ASTRIDE];
    __shared__ float Bs[2][BK * BSTRIDE];

    const int tid  = threadIdx.x;
    const int lane = tid & 31;
    const int wid  = tid >> 5;
    const int gid  = lane >> 2;    // group id 0..7
    const int tig  = lane & 3;     // thread in group 0..3

    const int m0 = blockIdx.y * BM;
    const int n0 = blockIdx.x * BN;

    const int wm = (wid >> 2) * 64;   // warp m offset: 0 or 64
    const int wn = (wid & 3) * 32;    // warp n offset: 0,32,64,96

    // staging indices
    const int a_row = tid >> 2;          // 0..63   (row for l-th chunk: +64*l)
    const int a_c4  = tid & 3;           // 0..3
    const int b_row = tid >> 5;          // 0..7    (+8*l)
    const int b_c4  = tid & 31;          // 0..31

    float acc[4][4][4];
    #pragma unroll
    for (int i = 0; i < 4; i++)
        #pragma unroll
        for (int j = 0; j < 4; j++)
            #pragma unroll
            for (int r = 0; r < 4; r++) acc[i][j][r] = 0.0f;

    const int nTiles = Kd / BK;

    // ---- async tile loader ----
    auto load_tile = [&](int t, int buf) {
        const float* Ag = A + (size_t)(m0) * Kd + t * BK;
        const float* Bg = B + (size_t)(t * BK) * Nd + n0;
        #pragma unroll
        for (int l = 0; l < 2; l++) {
            int row = a_row + l * 64;
            uint32_t sa = (uint32_t)__cvta_generic_to_shared(
                &As[buf][row * ASTRIDE + a_c4 * 4]);
            const float* ga = Ag + (size_t)row * Kd + a_c4 * 4;
            asm volatile("cp.async.cg.shared.global [%0], [%1], 16;\n"
                         :: "r"(sa), "l"(ga));
        }
        #pragma unroll
        for (int l = 0; l < 2; l++) {
            int row = b_row + l * 8;
            uint32_t sb = (uint32_t)__cvta_generic_to_shared(
                &Bs[buf][row * BSTRIDE + b_c4 * 4]);
            const float* gb = Bg + (size_t)row * Nd + b_c4 * 4;
            asm volatile("cp.async.cg.shared.global [%0], [%1], 16;\n"
                         :: "r"(sb), "l"(gb));
        }
        asm volatile("cp.async.commit_group;\n");
    };

    load_tile(0, 0);

    for (int t = 0; t < nTiles; t++) {
        const int cur = t & 1;
        if (t + 1 < nTiles) {
            load_tile(t + 1, cur ^ 1);
            asm volatile("cp.async.wait_group 1;\n");
        } else {
            asm volatile("cp.async.wait_group 0;\n");
        }
        __syncthreads();

        const float* Ab = As[cur];
        const float* Bb = Bs[cur];

        #pragma unroll
        for (int ks = 0; ks < BK; ks += 8) {
            uint32_t af[4][4];
            #pragma unroll
            for (int mt = 0; mt < 4; mt++) {
                int r0 = wm + mt * 16 + gid;
                af[mt][0] = f2tf32(Ab[(r0    ) * ASTRIDE + ks + tig    ]);
                af[mt][1] = f2tf32(Ab[(r0 + 8) * ASTRIDE + ks + tig    ]);
                af[mt][2] = f2tf32(Ab[(r0    ) * ASTRIDE + ks + tig + 4]);
                af[mt][3] = f2tf32(Ab[(r0 + 8) * ASTRIDE + ks + tig + 4]);
            }
            uint32_t bf[4][2];
            #pragma unroll
            for (int nt = 0; nt < 4; nt++) {
                int c0 = wn + nt * 8 + gid;
                bf[nt][0] = f2tf32(Bb[(ks + tig    ) * BSTRIDE + c0]);
                bf[nt][1] = f2tf32(Bb[(ks + tig + 4) * BSTRIDE + c0]);
            }
            #pragma unroll
            for (int mt = 0; mt < 4; mt++)
                #pragma unroll
                for (int nt = 0; nt < 4; nt++) {
                    asm volatile(
                        "mma.sync.aligned.m16n8k8.row.col.f32.tf32.tf32.f32 "
                        "{%0,%1,%2,%3}, {%4,%5,%6,%7}, {%8,%9}, {%0,%1,%2,%3};\n"
                        : "+f"(acc[mt][nt][0]), "+f"(acc[mt][nt][1]),
                          "+f"(acc[mt][nt][2]), "+f"(acc[mt][nt][3])
                        : "r"(af[mt][0]), "r"(af[mt][1]),
                          "r"(af[mt][2]), "r"(af[mt][3]),
                          "r"(bf[nt][0]), "r"(bf[nt][1]));
                }
        }
        __syncthreads();
    }

    // ---- epilogue: bias (+ReLU), direct global stores ----
    #pragma unroll
    for (int nt = 0; nt < 4; nt++) {
        int col = n0 + wn + nt * 8 + 2 * tig;
        float b0 = bias[col];
        float b1 = bias[col + 1];
        #pragma unroll
        for (int mt = 0; mt < 4; mt++) {
            int row = m0 + wm + mt * 16 + gid;
            float2 v0, v1;
            v0.x = acc[mt][nt][0] + b0;
            v0.y = acc[mt][nt][1] + b1;
            v1.x = acc[mt][nt][2] + b0;
            v1.y = acc[mt][nt][3] + b1;
            if (RELU) {
                v0.x = fmaxf(v0.x, 0.0f); v0.y = fmaxf(v0.y, 0.0f);
                v1.x = fmaxf(v1.x, 0.0f); v1.y = fmaxf(v1.y, 0.0f);
            }
            *(float2*)(C + (size_t)row * Nd + col)       = v0;
            *(float2*)(C + (size_t)(row + 8) * Nd + col) = v1;
        }
    }
}

// ---------------------------------------------------------------------------
// Fused causal attention, one CTA (128 threads) per (n, h, q).
// scale = 1/sqrt(E) = 1/32 (reference divides by sqrt(embed_size))
// ---------------------------------------------------------------------------
__global__ __launch_bounds__(128)
void attn_kernel(const float* __restrict__ Q, const float* __restrict__ K,
                 const float* __restrict__ V, float* __restrict__ O)
{
    __shared__ float sh_q[D_DIM];
    __shared__ float lg[S_LEN];
    __shared__ float sred[128];

    int qi = blockIdx.x;
    int h  = blockIdx.y;
    int n  = blockIdx.z;
    int tid = threadIdx.x;

    const size_t base = ((size_t)n * S_LEN) * E_DIM + h * D_DIM;
    const float scale = 1.0f / 32.0f;

    if (tid < D_DIM)
        sh_q[tid] = Q[base + (size_t)qi * E_DIM + tid];
    __syncthreads();

    int nk = qi + 1;

    for (int k = tid; k < nk; k += 128) {
        const float* krow = K + base + (size_t)k * E_DIM;
        float dot = 0.0f;
        #pragma unroll
        for (int d4 = 0; d4 < D_DIM; d4 += 4) {
            float4 kv = *(const float4*)(krow + d4);
            float4 qv = *(const float4*)(sh_q + d4);
            dot = fmaf(kv.x, qv.x, dot);
            dot = fmaf(kv.y, qv.y, dot);
            dot = fmaf(kv.z, qv.z, dot);
            dot = fmaf(kv.w, qv.w, dot);
        }
        lg[k] = dot * scale;
    }
    __syncthreads();

    float lmax = -1e30f;
    for (int k = tid; k < nk; k += 128) lmax = fmaxf(lmax, lg[k]);
    sred[tid] = lmax;
    __syncthreads();
    #pragma unroll
    for (int s = 64; s > 0; s >>= 1) {
        if (tid < s) sred[tid] = fmaxf(sred[tid], sred[tid + s]);
        __syncthreads();
    }
    float mx = sred[0];
    __syncthreads();

    float lsum = 0.0f;
    for (int k = tid; k < nk; k += 128) {
        float p = expf(lg[k] - mx);
        lg[k] = p;
        lsum += p;
    }
    sred[tid] = lsum;
    __syncthreads();
    #pragma unroll
    for (int s = 64; s > 0; s >>= 1) {
        if (tid < s) sred[tid] += sred[tid + s];
        __syncthreads();
    }
    float inv = 1.0f / sred[0];
    __syncthreads();

    int d = tid & 63;
    int half = tid >> 6;
    float acc = 0.0f;
    for (int k = half; k < nk; k += 2)
        acc = fmaf(lg[k], V[base + (size_t)k * E_DIM + d], acc);
    sred[tid] = acc;
    __syncthreads();
    if (tid < D_DIM)
        O[base + (size_t)qi * E_DIM + tid] = (sred[tid] + sred[tid + 64]) * inv;
}

// ---------------------------------------------------------------------------
// Residual add + LayerNorm
// ---------------------------------------------------------------------------
__global__ __launch_bounds__(256)
void add_ln_kernel(const float* __restrict__ a, const float* __restrict__ b,
                   const float* __restrict__ g, const float* __restrict__ beta,
                   float* __restrict__ out)
{
    __shared__ float sred[256];
    int row = blockIdx.x;
    int tid = threadIdx.x;
    const float* ar = a + (size_t)row * E_DIM;
    const float* br = b + (size_t)row * E_DIM;
    float* orow = out + (size_t)row * E_DIM;

    float xv[4];
    float lsum = 0.0f;
    #pragma unroll
    for (int j = 0; j < 4; j++) {
        int e = tid + j * 256;
        xv[j] = ar[e] + br[e];
        lsum += xv[j];
    }
    sred[tid] = lsum;
    __syncthreads();
    #pragma unroll
    for (int s = 128; s > 0; s >>= 1) {
        if (tid < s) sred[tid] += sred[tid + s];
        __syncthreads();
    }
    float mean = sred[0] * (1.0f / E_DIM);
    __syncthreads();

    float lvar = 0.0f;
    #pragma unroll
    for (int j = 0; j < 4; j++) {
        float d = xv[j] - mean;
        lvar += d * d;
    }
    sred[tid] = lvar;
    __syncthreads();
    #pragma unroll
    for (int s = 128; s > 0; s >>= 1) {
        if (tid < s) sred[tid] += sred[tid + s];
        __syncthreads();
    }
    float rstd = rsqrtf(sred[0] * (1.0f / E_DIM) + 1e-5f);

    #pragma unroll
    for (int j = 0; j < 4; j++) {
        int e = tid + j * 256;
        orow[e] = (xv[j] - mean) * rstd * g[e] + beta[e];
    }
}

// ---------------------------------------------------------------------------
// Launch
// ---------------------------------------------------------------------------
extern "C" void kernel_launch(void* const* d_in, const int* in_sizes, int n_in,
                              void* d_out, int out_size)
{
    const int*   x    = (const int*)  d_in[0];
    const float* emb  = (const float*)d_in[1];
    const float* Wq   = (const float*)d_in[2];
    const float* bq   = (const float*)d_in[3];
    const float* Wk   = (const float*)d_in[4];
    const float* bk   = (const float*)d_in[5];
    const float* Wv   = (const float*)d_in[6];
    const float* bv   = (const float*)d_in[7];
    const float* Wo   = (const float*)d_in[8];
    const float* bo   = (const float*)d_in[9];
    const float* ln1g = (const float*)d_in[10];
    const float* ln1b = (const float*)d_in[11];
    const float* ln2g = (const float*)d_in[12];
    const float* ln2b = (const float*)d_in[13];
    const float* W1   = (const float*)d_in[14];
    const float* b1   = (const float*)d_in[15];
    const float* W2   = (const float*)d_in[16];
    const float* b2   = (const float*)d_in[17];
    const float* Wout = (const float*)d_in[18];
    const float* bout = (const float*)d_in[19];
    float* out = (float*)d_out;

    float *act, *q, *k, *v, *attn, *tmp, *hbuf, *ff;
    cudaGetSymbolAddress((void**)&act,  g_act);
    cudaGetSymbolAddress((void**)&q,    g_q);
    cudaGetSymbolAddress((void**)&k,    g_k);
    cudaGetSymbolAddress((void**)&v,    g_v);
    cudaGetSymbolAddress((void**)&attn, g_attn);
    cudaGetSymbolAddress((void**)&tmp,  g_tmp);
    cudaGetSymbolAddress((void**)&hbuf, g_h);
    cudaGetSymbolAddress((void**)&ff,   g_ff);

    embed_kernel<<<M_TOK, 256>>>(x, emb, act);

    dim3 gE (E_DIM  / BN, M_TOK / BM);
    dim3 gFF(FF_DIM / BN, M_TOK / BM);
    dim3 gV (V_DIM  / BN, M_TOK / BM);

    for (int i = 0; i < L_NUM; i++) {
        size_t wo = (size_t)i * E_DIM * E_DIM;
        size_t bo_off = (size_t)i * E_DIM;

        tgemm_bias<0><<<gE, 256>>>(act, Wq + wo, bq + bo_off, q,    M_TOK, E_DIM, E_DIM);
        tgemm_bias<0><<<gE, 256>>>(act, Wk + wo, bk + bo_off, k,    M_TOK, E_DIM, E_DIM);
        tgemm_bias<0><<<gE, 256>>>(act, Wv + wo, bv + bo_off, v,    M_TOK, E_DIM, E_DIM);

        attn_kernel<<<dim3(S_LEN, H_DIM, N_B), 128>>>(q, k, v, attn);

        tgemm_bias<0><<<gE, 256>>>(attn, Wo + wo, bo + bo_off, tmp, M_TOK, E_DIM, E_DIM);

        add_ln_kernel<<<M_TOK, 256>>>(tmp, act, ln1g + bo_off, ln1b + bo_off, hbuf);

        tgemm_bias<1><<<gFF, 256>>>(hbuf, W1 + (size_t)i * E_DIM * FF_DIM,
                                    b1 + (size_t)i * FF_DIM, ff, M_TOK, FF_DIM, E_DIM);
        tgemm_bias<0><<<gE, 256>>>(ff, W2 + (size_t)i * FF_DIM * E_DIM,
                                   b2 + bo_off, tmp, M_TOK, E_DIM, FF_DIM);

        add_ln_kernel<<<M_TOK, 256>>>(tmp, hbuf, ln2g + bo_off, ln2b + bo_off, act);
    }

    tgemm_bias<0><<<gV, 256>>>(act, Wout, bout, out, M_TOK, V_DIM, E_DIM);
}

// round 4
// speedup vs baseline: 4.8997x; 2.7950x over previous
#include <cuda_runtime.h>
#include <math.h>
#include <stdint.h>

#define E_DIM 1024
#define H_DIM 16
#define D_DIM 64
#define S_LEN 1024
#define N_B   4
#define L_NUM 4
#define FF_DIM 4096
#define V_DIM 32000
#define M_TOK (N_B * S_LEN)   // 4096 token rows

// ---------------------------------------------------------------------------
// Scratch (device globals; no allocations allowed)
// ---------------------------------------------------------------------------
__device__ float g_act [M_TOK * E_DIM];
__device__ float g_q   [M_TOK * E_DIM];
__device__ float g_k   [M_TOK * E_DIM];
__device__ float g_v   [M_TOK * E_DIM];
__device__ float g_attn[M_TOK * E_DIM];
__device__ float g_tmp [M_TOK * E_DIM];
__device__ float g_h   [M_TOK * E_DIM];
__device__ float g_ff  [M_TOK * FF_DIM];

__device__ __forceinline__ uint32_t f2tf32(float x) {
    uint32_t r;
    asm("cvt.rna.tf32.f32 %0, %1;" : "=r"(r) : "f"(x));
    return r;
}

// ---------------------------------------------------------------------------
// Embedding + sinusoidal positional encoding
// ---------------------------------------------------------------------------
__global__ void embed_kernel(const int* __restrict__ x,
                             const float* __restrict__ emb,
                             float* __restrict__ out)
{
    int row = blockIdx.x;
    int s   = row & (S_LEN - 1);
    int tok = x[row];
    const float* erow = emb + (size_t)tok * E_DIM;
    float* orow = out + (size_t)row * E_DIM;

    int e0 = threadIdx.x * 4;
    #pragma unroll
    for (int j = 0; j < 4; j++) {
        int e = e0 + j;
        int even = e & ~1;
        float expo = (float)even / (float)E_DIM;
        float denom = powf(10000.0f, expo);
        float ang = (float)s / denom;
        float pe = (e & 1) ? cosf(ang) : sinf(ang);
        orow[e] = erow[e] + pe;
    }
}

// ---------------------------------------------------------------------------
// TF32 tensor-core GEMM (unchanged from round 2)
// ---------------------------------------------------------------------------
#define BM 128
#define BN 128
#define BK 16
#define ASTRIDE 20
#define BSTRIDE 136

template<int RELU>
__global__ __launch_bounds__(256)
void tgemm_bias(const float* __restrict__ A, const float* __restrict__ B,
                const float* __restrict__ bias, float* __restrict__ C,
                int Md, int Nd, int Kd)
{
    __shared__ float As[2][BM * ASTRIDE];
    __shared__ float Bs[2][BK * BSTRIDE];

    const int tid  = threadIdx.x;
    const int lane = tid & 31;
    const int wid  = tid >> 5;
    const int gid  = lane >> 2;
    const int tig  = lane & 3;

    const int m0 = blockIdx.y * BM;
    const int n0 = blockIdx.x * BN;

    const int wm = (wid >> 2) * 64;
    const int wn = (wid & 3) * 32;

    const int a_row = tid >> 2;
    const int a_c4  = tid & 3;
    const int b_row = tid >> 5;
    const int b_c4  = tid & 31;

    float acc[4][4][4];
    #pragma unroll
    for (int i = 0; i < 4; i++)
        #pragma unroll
        for (int j = 0; j < 4; j++)
            #pragma unroll
            for (int r = 0; r < 4; r++) acc[i][j][r] = 0.0f;

    const int nTiles = Kd / BK;

    auto load_tile = [&](int t, int buf) {
        const float* Ag = A + (size_t)(m0) * Kd + t * BK;
        const float* Bg = B + (size_t)(t * BK) * Nd + n0;
        #pragma unroll
        for (int l = 0; l < 2; l++) {
            int row = a_row + l * 64;
            uint32_t sa = (uint32_t)__cvta_generic_to_shared(
                &As[buf][row * ASTRIDE + a_c4 * 4]);
            const float* ga = Ag + (size_t)row * Kd + a_c4 * 4;
            asm volatile("cp.async.cg.shared.global [%0], [%1], 16;\n"
                         :: "r"(sa), "l"(ga));
        }
        #pragma unroll
        for (int l = 0; l < 2; l++) {
            int row = b_row + l * 8;
            uint32_t sb = (uint32_t)__cvta_generic_to_shared(
                &Bs[buf][row * BSTRIDE + b_c4 * 4]);
            const float* gb = Bg + (size_t)row * Nd + b_c4 * 4;
            asm volatile("cp.async.cg.shared.global [%0], [%1], 16;\n"
                         :: "r"(sb), "l"(gb));
        }
        asm volatile("cp.async.commit_group;\n");
    };

    load_tile(0, 0);

    for (int t = 0; t < nTiles; t++) {
        const int cur = t & 1;
        if (t + 1 < nTiles) {
            load_tile(t + 1, cur ^ 1);
            asm volatile("cp.async.wait_group 1;\n");
        } else {
            asm volatile("cp.async.wait_group 0;\n");
        }
        __syncthreads();

        const float* Ab = As[cur];
        const float* Bb = Bs[cur];

        #pragma unroll
        for (int ks = 0; ks < BK; ks += 8) {
            uint32_t af[4][4];
            #pragma unroll
            for (int mt = 0; mt < 4; mt++) {
                int r0 = wm + mt * 16 + gid;
                af[mt][0] = f2tf32(Ab[(r0    ) * ASTRIDE + ks + tig    ]);
                af[mt][1] = f2tf32(Ab[(r0 + 8) * ASTRIDE + ks + tig    ]);
                af[mt][2] = f2tf32(Ab[(r0    ) * ASTRIDE + ks + tig + 4]);
                af[mt][3] = f2tf32(Ab[(r0 + 8) * ASTRIDE + ks + tig + 4]);
            }
            uint32_t bf[4][2];
            #pragma unroll
            for (int nt = 0; nt < 4; nt++) {
                int c0 = wn + nt * 8 + gid;
                bf[nt][0] = f2tf32(Bb[(ks + tig    ) * BSTRIDE + c0]);
                bf[nt][1] = f2tf32(Bb[(ks + tig + 4) * BSTRIDE + c0]);
            }
            #pragma unroll
            for (int mt = 0; mt < 4; mt++)
                #pragma unroll
                for (int nt = 0; nt < 4; nt++) {
                    asm volatile(
                        "mma.sync.aligned.m16n8k8.row.col.f32.tf32.tf32.f32 "
                        "{%0,%1,%2,%3}, {%4,%5,%6,%7}, {%8,%9}, {%0,%1,%2,%3};\n"
                        : "+f"(acc[mt][nt][0]), "+f"(acc[mt][nt][1]),
                          "+f"(acc[mt][nt][2]), "+f"(acc[mt][nt][3])
                        : "r"(af[mt][0]), "r"(af[mt][1]),
                          "r"(af[mt][2]), "r"(af[mt][3]),
                          "r"(bf[nt][0]), "r"(bf[nt][1]));
                }
        }
        __syncthreads();
    }

    #pragma unroll
    for (int nt = 0; nt < 4; nt++) {
        int col = n0 + wn + nt * 8 + 2 * tig;
        float b0 = bias[col];
        float b1 = bias[col + 1];
        #pragma unroll
        for (int mt = 0; mt < 4; mt++) {
            int row = m0 + wm + mt * 16 + gid;
            float2 v0, v1;
            v0.x = acc[mt][nt][0] + b0;
            v0.y = acc[mt][nt][1] + b1;
            v1.x = acc[mt][nt][2] + b0;
            v1.y = acc[mt][nt][3] + b1;
            if (RELU) {
                v0.x = fmaxf(v0.x, 0.0f); v0.y = fmaxf(v0.y, 0.0f);
                v1.x = fmaxf(v1.x, 0.0f); v1.y = fmaxf(v1.y, 0.0f);
            }
            *(float2*)(C + (size_t)row * Nd + col)       = v0;
            *(float2*)(C + (size_t)(row + 8) * Nd + col) = v1;
        }
    }
}

// ---------------------------------------------------------------------------
// Flash attention (tf32 MMA). One CTA per (n, h, q-tile of 128).
// 256 threads = 8 warps; warp w owns query rows [16w, 16w+16).
// SMEM strides: Q/K 68, V 72, P 132 (conflict-free fragment patterns).
// scale (1/sqrt(E)=1/32) folded into Q at load.
// ---------------------------------------------------------------------------
#define QSTR 68
#define KSTR 68
#define VSTR 72
#define PSTR 132
#define ATTN_SMEM ((128*QSTR + 128*KSTR + 128*VSTR + 128*PSTR) * 4)

__global__ __launch_bounds__(256)
void flash_attn(const float* __restrict__ Q, const float* __restrict__ K,
                const float* __restrict__ V, float* __restrict__ O)
{
    extern __shared__ float sm[];
    float* Qs = sm;                       // [128][68], tf32 bits
    float* Ks = Qs + 128 * QSTR;          // [128][68], tf32 bits
    float* Vs = Ks + 128 * KSTR;          // [128][72], tf32 bits
    float* Ps = Vs + 128 * VSTR;          // [128][132], tf32 bits

    const int tid  = threadIdx.x;
    const int lane = tid & 31;
    const int wid  = tid >> 5;
    const int gid  = lane >> 2;
    const int tig  = lane & 3;

    const int qt = gridDim.x - 1 - blockIdx.x;   // big tiles first
    const int h  = blockIdx.y;
    const int n  = blockIdx.z;
    const size_t base = ((size_t)n * S_LEN) * E_DIM + h * D_DIM;
    const float scale = 1.0f / 32.0f;
    const int wrow = wid * 16;

    // ---- load Q tile (scaled + tf32) ----
    #pragma unroll
    for (int l = 0; l < 8; l++) {
        int idx = tid + l * 256;
        int r = idx >> 4, c4 = (idx & 15) * 4;
        float4 v = *(const float4*)(Q + base + (size_t)(qt * 128 + r) * E_DIM + c4);
        uint4 u;
        u.x = f2tf32(v.x * scale); u.y = f2tf32(v.y * scale);
        u.z = f2tf32(v.z * scale); u.w = f2tf32(v.w * scale);
        *(uint4*)(Qs + r * QSTR + c4) = u;
    }

    float accO[8][4];
    #pragma unroll
    for (int i = 0; i < 8; i++)
        #pragma unroll
        for (int j = 0; j < 4; j++) accO[i][j] = 0.0f;
    float m0 = -1e30f, m1 = -1e30f, l0 = 0.0f, l1 = 0.0f;

    const int rbase = wrow + gid;

    for (int kt = 0; kt <= qt; kt++) {
        __syncthreads();   // previous iteration's readers done
        #pragma unroll
        for (int l = 0; l < 8; l++) {
            int idx = tid + l * 256;
            int r = idx >> 4, c4 = (idx & 15) * 4;
            const size_t goff = base + (size_t)(kt * 128 + r) * E_DIM + c4;
            float4 kv = *(const float4*)(K + goff);
            uint4 ku;
            ku.x = f2tf32(kv.x); ku.y = f2tf32(kv.y);
            ku.z = f2tf32(kv.z); ku.w = f2tf32(kv.w);
            *(uint4*)(Ks + r * KSTR + c4) = ku;
            float4 vv = *(const float4*)(V + goff);
            uint4 vu;
            vu.x = f2tf32(vv.x); vu.y = f2tf32(vv.y);
            vu.z = f2tf32(vv.z); vu.w = f2tf32(vv.w);
            *(uint4*)(Vs + r * VSTR + c4) = vu;
        }
        __syncthreads();

        // ---- S = Q K^T for this warp's 16 rows x 128 key cols ----
        float accS[16][4];
        #pragma unroll
        for (int i = 0; i < 16; i++)
            #pragma unroll
            for (int j = 0; j < 4; j++) accS[i][j] = 0.0f;

        #pragma unroll
        for (int ks = 0; ks < 8; ks++) {
            uint32_t a0 = *(const uint32_t*)(Qs + (rbase    ) * QSTR + ks * 8 + tig);
            uint32_t a1 = *(const uint32_t*)(Qs + (rbase + 8) * QSTR + ks * 8 + tig);
            uint32_t a2 = *(const uint32_t*)(Qs + (rbase    ) * QSTR + ks * 8 + tig + 4);
            uint32_t a3 = *(const uint32_t*)(Qs + (rbase + 8) * QSTR + ks * 8 + tig + 4);
            #pragma unroll
            for (int nt = 0; nt < 16; nt++) {
                uint32_t b0 = *(const uint32_t*)(Ks + (nt * 8 + gid) * KSTR + ks * 8 + tig);
                uint32_t b1 = *(const uint32_t*)(Ks + (nt * 8 + gid) * KSTR + ks * 8 + tig + 4);
                asm volatile(
                    "mma.sync.aligned.m16n8k8.row.col.f32.tf32.tf32.f32 "
                    "{%0,%1,%2,%3}, {%4,%5,%6,%7}, {%8,%9}, {%0,%1,%2,%3};\n"
                    : "+f"(accS[nt][0]), "+f"(accS[nt][1]),
                      "+f"(accS[nt][2]), "+f"(accS[nt][3])
                    : "r"(a0), "r"(a1), "r"(a2), "r"(a3), "r"(b0), "r"(b1));
            }
        }

        // ---- causal mask on diagonal tile ----
        if (kt == qt) {
            #pragma unroll
            for (int nt = 0; nt < 16; nt++) {
                int c = nt * 8 + 2 * tig;
                if (c     > rbase    ) accS[nt][0] = -1e30f;
                if (c + 1 > rbase    ) accS[nt][1] = -1e30f;
                if (c     > rbase + 8) accS[nt][2] = -1e30f;
                if (c + 1 > rbase + 8) accS[nt][3] = -1e30f;
            }
        }

        // ---- online softmax ----
        float mx0 = -1e30f, mx1 = -1e30f;
        #pragma unroll
        for (int nt = 0; nt < 16; nt++) {
            mx0 = fmaxf(mx0, fmaxf(accS[nt][0], accS[nt][1]));
            mx1 = fmaxf(mx1, fmaxf(accS[nt][2], accS[nt][3]));
        }
        mx0 = fmaxf(mx0, __shfl_xor_sync(0xffffffffu, mx0, 1));
        mx0 = fmaxf(mx0, __shfl_xor_sync(0xffffffffu, mx0, 2));
        mx1 = fmaxf(mx1, __shfl_xor_sync(0xffffffffu, mx1, 1));
        mx1 = fmaxf(mx1, __shfl_xor_sync(0xffffffffu, mx1, 2));

        float mn0 = fmaxf(m0, mx0), mn1 = fmaxf(m1, mx1);
        float al0 = __expf(m0 - mn0), al1 = __expf(m1 - mn1);
        m0 = mn0; m1 = mn1;

        float s0 = 0.0f, s1 = 0.0f;
        #pragma unroll
        for (int nt = 0; nt < 16; nt++) {
            float p0 = __expf(accS[nt][0] - mn0);
            float p1 = __expf(accS[nt][1] - mn0);
            float p2 = __expf(accS[nt][2] - mn1);
            float p3 = __expf(accS[nt][3] - mn1);
            accS[nt][0] = p0; accS[nt][1] = p1;
            accS[nt][2] = p2; accS[nt][3] = p3;
            s0 += p0 + p1; s1 += p2 + p3;
        }
        s0 += __shfl_xor_sync(0xffffffffu, s0, 1);
        s0 += __shfl_xor_sync(0xffffffffu, s0, 2);
        s1 += __shfl_xor_sync(0xffffffffu, s1, 1);
        s1 += __shfl_xor_sync(0xffffffffu, s1, 2);
        l0 = l0 * al0 + s0;
        l1 = l1 * al1 + s1;

        #pragma unroll
        for (int i = 0; i < 8; i++) {
            accO[i][0] *= al0; accO[i][1] *= al0;
            accO[i][2] *= al1; accO[i][3] *= al1;
        }

        // ---- P to SMEM (tf32), own-warp region only ----
        #pragma unroll
        for (int nt = 0; nt < 16; nt++) {
            uint2 pa, pb;
            pa.x = f2tf32(accS[nt][0]); pa.y = f2tf32(accS[nt][1]);
            pb.x = f2tf32(accS[nt][2]); pb.y = f2tf32(accS[nt][3]);
            *(uint2*)(Ps + (rbase    ) * PSTR + nt * 8 + 2 * tig) = pa;
            *(uint2*)(Ps + (rbase + 8) * PSTR + nt * 8 + 2 * tig) = pb;
        }
        __syncwarp();

        // ---- O += P V ----
        #pragma unroll
        for (int ki = 0; ki < 16; ki++) {
            uint32_t a0 = *(const uint32_t*)(Ps + (rbase    ) * PSTR + ki * 8 + tig);
            uint32_t a1 = *(const uint32_t*)(Ps + (rbase + 8) * PSTR + ki * 8 + tig);
            uint32_t a2 = *(const uint32_t*)(Ps + (rbase    ) * PSTR + ki * 8 + tig + 4);
            uint32_t a3 = *(const uint32_t*)(Ps + (rbase + 8) * PSTR + ki * 8 + tig + 4);
            #pragma unroll
            for (int nt = 0; nt < 8; nt++) {
                uint32_t b0 = *(const uint32_t*)(Vs + (ki * 8 + tig    ) * VSTR + nt * 8 + gid);
                uint32_t b1 = *(const uint32_t*)(Vs + (ki * 8 + tig + 4) * VSTR + nt * 8 + gid);
                asm volatile(
                    "mma.sync.aligned.m16n8k8.row.col.f32.tf32.tf32.f32 "
                    "{%0,%1,%2,%3}, {%4,%5,%6,%7}, {%8,%9}, {%0,%1,%2,%3};\n"
                    : "+f"(accO[nt][0]), "+f"(accO[nt][1]),
                      "+f"(accO[nt][2]), "+f"(accO[nt][3])
                    : "r"(a0), "r"(a1), "r"(a2), "r"(a3), "r"(b0), "r"(b1));
            }
        }
    }

    // ---- writeback ----
    float inv0 = 1.0f / l0, inv1 = 1.0f / l1;
    #pragma unroll
    for (int nt = 0; nt < 8; nt++) {
        int col = nt * 8 + 2 * tig;
        float2 o0, o1;
        o0.x = accO[nt][0] * inv0; o0.y = accO[nt][1] * inv0;
        o1.x = accO[nt][2] * inv1; o1.y = accO[nt][3] * inv1;
        *(float2*)(O + base + (size_t)(qt * 128 + rbase    ) * E_DIM + col) = o0;
        *(float2*)(O + base + (size_t)(qt * 128 + rbase + 8) * E_DIM + col) = o1;
    }
}

// ---------------------------------------------------------------------------
// Residual add + LayerNorm
// ---------------------------------------------------------------------------
__global__ __launch_bounds__(256)
void add_ln_kernel(const float* __restrict__ a, const float* __restrict__ b,
                   const float* __restrict__ g, const float* __restrict__ beta,
                   float* __restrict__ out)
{
    __shared__ float sred[256];
    int row = blockIdx.x;
    int tid = threadIdx.x;
    const float* ar = a + (size_t)row * E_DIM;
    const float* br = b + (size_t)row * E_DIM;
    float* orow = out + (size_t)row * E_DIM;

    float xv[4];
    float lsum = 0.0f;
    #pragma unroll
    for (int j = 0; j < 4; j++) {
        int e = tid + j * 256;
        xv[j] = ar[e] + br[e];
        lsum += xv[j];
    }
    sred[tid] = lsum;
    __syncthreads();
    #pragma unroll
    for (int s = 128; s > 0; s >>= 1) {
        if (tid < s) sred[tid] += sred[tid + s];
        __syncthreads();
    }
    float mean = sred[0] * (1.0f / E_DIM);
    __syncthreads();

    float lvar = 0.0f;
    #pragma unroll
    for (int j = 0; j < 4; j++) {
        float d = xv[j] - mean;
        lvar += d * d;
    }
    sred[tid] = lvar;
    __syncthreads();
    #pragma unroll
    for (int s = 128; s > 0; s >>= 1) {
        if (tid < s) sred[tid] += sred[tid + s];
        __syncthreads();
    }
    float rstd = rsqrtf(sred[0] * (1.0f / E_DIM) + 1e-5f);

    #pragma unroll
    for (int j = 0; j < 4; j++) {
        int e = tid + j * 256;
        orow[e] = (xv[j] - mean) * rstd * g[e] + beta[e];
    }
}

// ---------------------------------------------------------------------------
// Launch
// ---------------------------------------------------------------------------
extern "C" void kernel_launch(void* const* d_in, const int* in_sizes, int n_in,
                              void* d_out, int out_size)
{
    const int*   x    = (const int*)  d_in[0];
    const float* emb  = (const float*)d_in[1];
    const float* Wq   = (const float*)d_in[2];
    const float* bq   = (const float*)d_in[3];
    const float* Wk   = (const float*)d_in[4];
    const float* bk   = (const float*)d_in[5];
    const float* Wv   = (const float*)d_in[6];
    const float* bv   = (const float*)d_in[7];
    const float* Wo   = (const float*)d_in[8];
    const float* bo   = (const float*)d_in[9];
    const float* ln1g = (const float*)d_in[10];
    const float* ln1b = (const float*)d_in[11];
    const float* ln2g = (const float*)d_in[12];
    const float* ln2b = (const float*)d_in[13];
    const float* W1   = (const float*)d_in[14];
    const float* b1   = (const float*)d_in[15];
    const float* W2   = (const float*)d_in[16];
    const float* b2   = (const float*)d_in[17];
    const float* Wout = (const float*)d_in[18];
    const float* bout = (const float*)d_in[19];
    float* out = (float*)d_out;

    float *act, *q, *k, *v, *attn, *tmp, *hbuf, *ff;
    cudaGetSymbolAddress((void**)&act,  g_act);
    cudaGetSymbolAddress((void**)&q,    g_q);
    cudaGetSymbolAddress((void**)&k,    g_k);
    cudaGetSymbolAddress((void**)&v,    g_v);
    cudaGetSymbolAddress((void**)&attn, g_attn);
    cudaGetSymbolAddress((void**)&tmp,  g_tmp);
    cudaGetSymbolAddress((void**)&hbuf, g_h);
    cudaGetSymbolAddress((void**)&ff,   g_ff);

    static int smem_set = 0;
    if (!smem_set) {
        cudaFuncSetAttribute(flash_attn,
                             cudaFuncAttributeMaxDynamicSharedMemorySize,
                             ATTN_SMEM);
        smem_set = 1;
    }

    embed_kernel<<<M_TOK, 256>>>(x, emb, act);

    dim3 gE (E_DIM  / BN, M_TOK / BM);
    dim3 gFF(FF_DIM / BN, M_TOK / BM);
    dim3 gV (V_DIM  / BN, M_TOK / BM);

    for (int i = 0; i < L_NUM; i++) {
        size_t wo = (size_t)i * E_DIM * E_DIM;
        size_t bo_off = (size_t)i * E_DIM;

        tgemm_bias<0><<<gE, 256>>>(act, Wq + wo, bq + bo_off, q,    M_TOK, E_DIM, E_DIM);
        tgemm_bias<0><<<gE, 256>>>(act, Wk + wo, bk + bo_off, k,    M_TOK, E_DIM, E_DIM);
        tgemm_bias<0><<<gE, 256>>>(act, Wv + wo, bv + bo_off, v,    M_TOK, E_DIM, E_DIM);

        flash_attn<<<dim3(S_LEN / 128, H_DIM, N_B), 256, ATTN_SMEM>>>(q, k, v, attn);

        tgemm_bias<0><<<gE, 256>>>(attn, Wo + wo, bo + bo_off, tmp, M_TOK, E_DIM, E_DIM);

        add_ln_kernel<<<M_TOK, 256>>>(tmp, act, ln1g + bo_off, ln1b + bo_off, hbuf);

        tgemm_bias<1><<<gFF, 256>>>(hbuf, W1 + (size_t)i * E_DIM * FF_DIM,
                                    b1 + (size_t)i * FF_DIM, ff, M_TOK, FF_DIM, E_DIM);
        tgemm_bias<0><<<gE, 256>>>(ff, W2 + (size_t)i * FF_DIM * E_DIM,
                                   b2 + bo_off, tmp, M_TOK, E_DIM, FF_DIM);

        add_ln_kernel<<<M_TOK, 256>>>(tmp, hbuf, ln2g + bo_off, ln2b + bo_off, act);
    }

    tgemm_bias<0><<<gV, 256>>>(act, Wout, bout, out, M_TOK, V_DIM, E_DIM);
}

// round 6
// speedup vs baseline: 7.8536x; 1.6029x over previous
#include <cuda_runtime.h>
#include <cuda_fp16.h>
#include <math.h>
#include <stdint.h>

#define E_DIM 1024
#define H_DIM 16
#define D_DIM 64
#define S_LEN 1024
#define N_B   4
#define L_NUM 4
#define FF_DIM 4096
#define V_DIM 32000
#define M_TOK (N_B * S_LEN)   // 4096 token rows

// ---------------------------------------------------------------------------
// Scratch (device globals; no allocations allowed)
// ---------------------------------------------------------------------------
__device__ float g_act [M_TOK * E_DIM];
__device__ float g_q   [M_TOK * E_DIM];
__device__ float g_k   [M_TOK * E_DIM];
__device__ float g_v   [M_TOK * E_DIM];
__device__ float g_attn[M_TOK * E_DIM];
__device__ float g_tmp [M_TOK * E_DIM];
__device__ float g_h   [M_TOK * E_DIM];
__device__ float g_ff  [M_TOK * FF_DIM];
__device__ float g_wt  [(size_t)V_DIM * E_DIM / 2]; // half scratch (cast), 65.5MB

__device__ __forceinline__ uint32_t f2tf32(float x) {
    uint32_t r;
    asm("cvt.rna.tf32.f32 %0, %1;" : "=r"(r) : "f"(x));
    return r;
}

__device__ __forceinline__ uint32_t smem_u32(const void* p) {
    uint32_t a;
    asm("{ .reg .u64 t; cvta.to.shared.u64 t, %1; cvt.u32.u64 %0, t; }"
        : "=r"(a) : "l"(p));
    return a;
}

__device__ __forceinline__ void ldsm_x4(uint32_t* r, uint32_t addr) {
    asm volatile("ldmatrix.sync.aligned.m8n8.x4.shared.b16 {%0,%1,%2,%3}, [%4];"
                 : "=r"(r[0]), "=r"(r[1]), "=r"(r[2]), "=r"(r[3]) : "r"(addr));
}
__device__ __forceinline__ void ldsm_x2(uint32_t* r, uint32_t addr) {
    asm volatile("ldmatrix.sync.aligned.m8n8.x2.shared.b16 {%0,%1}, [%2];"
                 : "=r"(r[0]), "=r"(r[1]) : "r"(addr));
}

// ---------------------------------------------------------------------------
// Embedding + sinusoidal positional encoding
// ---------------------------------------------------------------------------
__global__ void embed_kernel(const int* __restrict__ x,
                             const float* __restrict__ emb,
                             float* __restrict__ out)
{
    int row = blockIdx.x;
    int s   = row & (S_LEN - 1);
    int tok = x[row];
    const float* erow = emb + (size_t)tok * E_DIM;
    float* orow = out + (size_t)row * E_DIM;

    int e0 = threadIdx.x * 4;
    #pragma unroll
    for (int j = 0; j < 4; j++) {
        int e = e0 + j;
        int even = e & ~1;
        float expo = (float)even / (float)E_DIM;
        float denom = powf(10000.0f, expo);
        float ang = (float)s / denom;
        float pe = (e & 1) ? cosf(ang) : sinf(ang);
        orow[e] = erow[e] + pe;
    }
}

// ---------------------------------------------------------------------------
// Transpose + convert to half: Wt[n][k] = half(W[k][n]). W is [K,N] f32.
// grid (N/32, K/32), block (32,8)
// ---------------------------------------------------------------------------
__global__ __launch_bounds__(256)
void transpose_half(const float* __restrict__ W, __half* __restrict__ Wt,
                    int Kd, int Nd)
{
    __shared__ float tile[32][33];
    int n0 = blockIdx.x * 32, k0 = blockIdx.y * 32;
    int tx = threadIdx.x, ty = threadIdx.y;
    #pragma unroll
    for (int dy = 0; dy < 32; dy += 8)
        tile[ty + dy][tx] = W[(size_t)(k0 + ty + dy) * Nd + n0 + tx];
    __syncthreads();
    #pragma unroll
    for (int dy = 0; dy < 32; dy += 8)
        Wt[(size_t)(n0 + ty + dy) * Kd + k0 + tx] =
            __float2half_rn(tile[tx][ty + dy]);
}

// ---------------------------------------------------------------------------
// FP16 tensor-core GEMM via mma.sync m16n8k16 + ldmatrix.
// C[M,N] = A[M,K](f32) @ Bt[N,K](half)^T + bias, optional ReLU. f32 accum.
// CTA 128x128, BK=32, 256 threads (8 warps 2x4), warp tile 64x32.
// SMEM: A [m][k] half rows of 112B (64B data + pad), B [n][k] same.
// 112 = 7*16 -> ldmatrix row addresses conflict-free. Double buffered.
// ---------------------------------------------------------------------------
#define GBM 128
#define GBN 128
#define GBK 32
#define ROWB 112                         // bytes per SMEM row
#define A_ST (128 * ROWB)                // 14336
#define STAGE (2 * A_ST)                 // A + B per stage = 28672
#define GEMM_SMEM (2 * STAGE)            // 57344

template<int RELU>
__global__ __launch_bounds__(256, 2)
void hgemm_bias(const float* __restrict__ A, const __half* __restrict__ Bt,
                const float* __restrict__ bias, float* __restrict__ C,
                int Nd, int Kd)
{
    extern __shared__ char smem[];
    const uint32_t sbase = smem_u32(smem);

    const int tid  = threadIdx.x;
    const int lane = tid & 31;
    const int wid  = tid >> 5;
    const int gid  = lane >> 2;
    const int tig  = lane & 3;

    const int m0 = blockIdx.y * GBM;
    const int n0 = blockIdx.x * GBN;
    const int wm = (wid >> 2) * 64;
    const int wn = (wid & 3) * 32;

    // ldmatrix per-lane address components
    const int arow = wm + (lane & 15);
    const int akoh = (lane & 16) ? 8 : 0;
    const int brow = wn + (lane & 7);
    const int bkoh = (lane & 8) ? 8 : 0;

    // staging maps
    const int a_m  = tid >> 3;        // +32*p
    const int a_kc = tid & 7;         // k0 = kc*4
    const int b_n  = tid >> 2;        // +64*p
    const int b_kq = tid & 3;         // k0 = kq*8 halfs (16B)

    float acc[4][4][4];
    #pragma unroll
    for (int i = 0; i < 4; i++)
        #pragma unroll
        for (int j = 0; j < 4; j++)
            #pragma unroll
            for (int r = 0; r < 4; r++) acc[i][j][r] = 0.0f;

    const int nK = Kd / GBK;

    // ---- prologue: stage tile 0 ----
    {
        #pragma unroll
        for (int p = 0; p < 2; p++) {
            int n = b_n + p * 64;
            uint32_t dst = sbase + A_ST + n * ROWB + b_kq * 16;
            const __half* src = Bt + (size_t)(n0 + n) * Kd + b_kq * 8;
            asm volatile("cp.async.cg.shared.global [%0], [%1], 16;\n"
                         :: "r"(dst), "l"(src));
        }
        asm volatile("cp.async.commit_group;\n");
        #pragma unroll
        for (int p = 0; p < 4; p++) {
            int m = a_m + p * 32;
            float4 v = *(const float4*)(A + (size_t)(m0 + m) * Kd + a_kc * 4);
            __half2 h0 = __floats2half2_rn(v.x, v.y);
            __half2 h1 = __floats2half2_rn(v.z, v.w);
            uint2 u = { *(uint32_t*)&h0, *(uint32_t*)&h1 };
            *(uint2*)(smem + m * ROWB + a_kc * 8) = u;
        }
        asm volatile("cp.async.wait_group 0;\n");
        __syncthreads();
    }

    for (int t = 0; t < nK; t++) {
        const int cur = t & 1;
        const int nxt = cur ^ 1;
        const bool has_next = (t + 1 < nK);

        float4 areg[4];
        if (has_next) {
            #pragma unroll
            for (int p = 0; p < 2; p++) {
                int n = b_n + p * 64;
                uint32_t dst = sbase + nxt * STAGE + A_ST + n * ROWB + b_kq * 16;
                const __half* src = Bt + (size_t)(n0 + n) * Kd + (t + 1) * GBK + b_kq * 8;
                asm volatile("cp.async.cg.shared.global [%0], [%1], 16;\n"
                             :: "r"(dst), "l"(src));
            }
            asm volatile("cp.async.commit_group;\n");
            #pragma unroll
            for (int p = 0; p < 4; p++) {
                int m = a_m + p * 32;
                areg[p] = *(const float4*)(A + (size_t)(m0 + m) * Kd + (t + 1) * GBK + a_kc * 4);
            }
        }

        // ---- compute current tile ----
        const uint32_t sA = sbase + cur * STAGE;
        const uint32_t sB = sA + A_ST;
        #pragma unroll
        for (int ko = 0; ko < 32; ko += 16) {
            uint32_t af[4][4], bf[4][2];
            #pragma unroll
            for (int mt = 0; mt < 4; mt++)
                ldsm_x4(af[mt], sA + (arow + mt * 16) * ROWB + (ko + akoh) * 2);
            #pragma unroll
            for (int nt = 0; nt < 4; nt++)
                ldsm_x2(bf[nt], sB + (brow + nt * 8) * ROWB + (ko + bkoh) * 2);
            #pragma unroll
            for (int mt = 0; mt < 4; mt++)
                #pragma unroll
                for (int nt = 0; nt < 4; nt++) {
                    asm volatile(
                        "mma.sync.aligned.m16n8k16.row.col.f32.f16.f16.f32 "
                        "{%0,%1,%2,%3}, {%4,%5,%6,%7}, {%8,%9}, {%0,%1,%2,%3};\n"
                        : "+f"(acc[mt][nt][0]), "+f"(acc[mt][nt][1]),
                          "+f"(acc[mt][nt][2]), "+f"(acc[mt][nt][3])
                        : "r"(af[mt][0]), "r"(af[mt][1]),
                          "r"(af[mt][2]), "r"(af[mt][3]),
                          "r"(bf[nt][0]), "r"(bf[nt][1]));
                }
        }

        if (has_next) {
            char* dstA = smem + nxt * STAGE;
            #pragma unroll
            for (int p = 0; p < 4; p++) {
                int m = a_m + p * 32;
                __half2 h0 = __floats2half2_rn(areg[p].x, areg[p].y);
                __half2 h1 = __floats2half2_rn(areg[p].z, areg[p].w);
                uint2 u = { *(uint32_t*)&h0, *(uint32_t*)&h1 };
                *(uint2*)(dstA + m * ROWB + a_kc * 8) = u;
            }
            asm volatile("cp.async.wait_group 0;\n");
        }
        __syncthreads();
    }

    // ---- epilogue: bias (+ReLU) ----
    #pragma unroll
    for (int nt = 0; nt < 4; nt++) {
        int col = n0 + wn + nt * 8 + 2 * tig;
        float b0 = bias[col];
        float b1 = bias[col + 1];
        #pragma unroll
        for (int mt = 0; mt < 4; mt++) {
            int row = m0 + wm + mt * 16 + gid;
            float2 v0, v1;
            v0.x = acc[mt][nt][0] + b0;
            v0.y = acc[mt][nt][1] + b1;
            v1.x = acc[mt][nt][2] + b0;
            v1.y = acc[mt][nt][3] + b1;
            if (RELU) {
                v0.x = fmaxf(v0.x, 0.0f); v0.y = fmaxf(v0.y, 0.0f);
                v1.x = fmaxf(v1.x, 0.0f); v1.y = fmaxf(v1.y, 0.0f);
            }
            *(float2*)(C + (size_t)row * Nd + col)       = v0;
            *(float2*)(C + (size_t)(row + 8) * Nd + col) = v1;
        }
    }
}

// ---------------------------------------------------------------------------
// Flash attention (tf32 mma.sync) — unchanged
// ---------------------------------------------------------------------------
#define QSTR 68
#define KSTR 68
#define VSTR 72
#define PSTR 132
#define ATTN_SMEM ((128*QSTR + 128*KSTR + 128*VSTR + 128*PSTR) * 4)

__global__ __launch_bounds__(256)
void flash_attn(const float* __restrict__ Q, const float* __restrict__ K,
                const float* __restrict__ V, float* __restrict__ O)
{
    extern __shared__ float sm[];
    float* Qs = sm;
    float* Ks = Qs + 128 * QSTR;
    float* Vs = Ks + 128 * KSTR;
    float* Ps = Vs + 128 * VSTR;

    const int tid  = threadIdx.x;
    const int lane = tid & 31;
    const int wid  = tid >> 5;
    const int gid  = lane >> 2;
    const int tig  = lane & 3;

    const int qt = gridDim.x - 1 - blockIdx.x;
    const int h  = blockIdx.y;
    const int n  = blockIdx.z;
    const size_t base = ((size_t)n * S_LEN) * E_DIM + h * D_DIM;
    const float scale = 1.0f / 32.0f;
    const int wrow = wid * 16;

    #pragma unroll
    for (int l = 0; l < 8; l++) {
        int idx = tid + l * 256;
        int r = idx >> 4, c4 = (idx & 15) * 4;
        float4 v = *(const float4*)(Q + base + (size_t)(qt * 128 + r) * E_DIM + c4);
        uint4 u;
        u.x = f2tf32(v.x * scale); u.y = f2tf32(v.y * scale);
        u.z = f2tf32(v.z * scale); u.w = f2tf32(v.w * scale);
        *(uint4*)(Qs + r * QSTR + c4) = u;
    }

    float accO[8][4];
    #pragma unroll
    for (int i = 0; i < 8; i++)
        #pragma unroll
        for (int j = 0; j < 4; j++) accO[i][j] = 0.0f;
    float m0 = -1e30f, m1 = -1e30f, l0 = 0.0f, l1 = 0.0f;

    const int rbase = wrow + gid;

    for (int kt = 0; kt <= qt; kt++) {
        __syncthreads();
        #pragma unroll
        for (int l = 0; l < 8; l++) {
            int idx = tid + l * 256;
            int r = idx >> 4, c4 = (idx & 15) * 4;
            const size_t goff = base + (size_t)(kt * 128 + r) * E_DIM + c4;
            float4 kv = *(const float4*)(K + goff);
            uint4 ku;
            ku.x = f2tf32(kv.x); ku.y = f2tf32(kv.y);
            ku.z = f2tf32(kv.z); ku.w = f2tf32(kv.w);
            *(uint4*)(Ks + r * KSTR + c4) = ku;
            float4 vv = *(const float4*)(V + goff);
            uint4 vu;
            vu.x = f2tf32(vv.x); vu.y = f2tf32(vv.y);
            vu.z = f2tf32(vv.z); vu.w = f2tf32(vv.w);
            *(uint4*)(Vs + r * VSTR + c4) = vu;
        }
        __syncthreads();

        float accS[16][4];
        #pragma unroll
        for (int i = 0; i < 16; i++)
            #pragma unroll
            for (int j = 0; j < 4; j++) accS[i][j] = 0.0f;

        #pragma unroll
        for (int ks = 0; ks < 8; ks++) {
            uint32_t a0 = *(const uint32_t*)(Qs + (rbase    ) * QSTR + ks * 8 + tig);
            uint32_t a1 = *(const uint32_t*)(Qs + (rbase + 8) * QSTR + ks * 8 + tig);
            uint32_t a2 = *(const uint32_t*)(Qs + (rbase    ) * QSTR + ks * 8 + tig + 4);
            uint32_t a3 = *(const uint32_t*)(Qs + (rbase + 8) * QSTR + ks * 8 + tig + 4);
            #pragma unroll
            for (int nt = 0; nt < 16; nt++) {
                uint32_t b0 = *(const uint32_t*)(Ks + (nt * 8 + gid) * KSTR + ks * 8 + tig);
                uint32_t b1 = *(const uint32_t*)(Ks + (nt * 8 + gid) * KSTR + ks * 8 + tig + 4);
                asm volatile(
                    "mma.sync.aligned.m16n8k8.row.col.f32.tf32.tf32.f32 "
                    "{%0,%1,%2,%3}, {%4,%5,%6,%7}, {%8,%9}, {%0,%1,%2,%3};\n"
                    : "+f"(accS[nt][0]), "+f"(accS[nt][1]),
                      "+f"(accS[nt][2]), "+f"(accS[nt][3])
                    : "r"(a0), "r"(a1), "r"(a2), "r"(a3), "r"(b0), "r"(b1));
            }
        }

        if (kt == qt) {
            #pragma unroll
            for (int nt = 0; nt < 16; nt++) {
                int c = nt * 8 + 2 * tig;
                if (c     > rbase    ) accS[nt][0] = -1e30f;
                if (c + 1 > rbase    ) accS[nt][1] = -1e30f;
                if (c     > rbase + 8) accS[nt][2] = -1e30f;
                if (c + 1 > rbase + 8) accS[nt][3] = -1e30f;
            }
        }

        float mx0 = -1e30f, mx1 = -1e30f;
        #pragma unroll
        for (int nt = 0; nt < 16; nt++) {
            mx0 = fmaxf(mx0, fmaxf(accS[nt][0], accS[nt][1]));
            mx1 = fmaxf(mx1, fmaxf(accS[nt][2], accS[nt][3]));
        }
        mx0 = fmaxf(mx0, __shfl_xor_sync(0xffffffffu, mx0, 1));
        mx0 = fmaxf(mx0, __shfl_xor_sync(0xffffffffu, mx0, 2));
        mx1 = fmaxf(mx1, __shfl_xor_sync(0xffffffffu, mx1, 1));
        mx1 = fmaxf(mx1, __shfl_xor_sync(0xffffffffu, mx1, 2));

        float mn0 = fmaxf(m0, mx0), mn1 = fmaxf(m1, mx1);
        float al0 = __expf(m0 - mn0), al1 = __expf(m1 - mn1);
        m0 = mn0; m1 = mn1;

        float s0 = 0.0f, s1 = 0.0f;
        #pragma unroll
        for (int nt = 0; nt < 16; nt++) {
            float p0 = __expf(accS[nt][0] - mn0);
            float p1 = __expf(accS[nt][1] - mn0);
            float p2 = __expf(accS[nt][2] - mn1);
            float p3 = __expf(accS[nt][3] - mn1);
            accS[nt][0] = p0; accS[nt][1] = p1;
            accS[nt][2] = p2; accS[nt][3] = p3;
            s0 += p0 + p1; s1 += p2 + p3;
        }
        s0 += __shfl_xor_sync(0xffffffffu, s0, 1);
        s0 += __shfl_xor_sync(0xffffffffu, s0, 2);
        s1 += __shfl_xor_sync(0xffffffffu, s1, 1);
        s1 += __shfl_xor_sync(0xffffffffu, s1, 2);
        l0 = l0 * al0 + s0;
        l1 = l1 * al1 + s1;

        #pragma unroll
        for (int i = 0; i < 8; i++) {
            accO[i][0] *= al0; accO[i][1] *= al0;
            accO[i][2] *= al1; accO[i][3] *= al1;
        }

        #pragma unroll
        for (int nt = 0; nt < 16; nt++) {
            uint2 pa, pb;
            pa.x = f2tf32(accS[nt][0]); pa.y = f2tf32(accS[nt][1]);
            pb.x = f2tf32(accS[nt][2]); pb.y = f2tf32(accS[nt][3]);
            *(uint2*)(Ps + (rbase    ) * PSTR + nt * 8 + 2 * tig) = pa;
            *(uint2*)(Ps + (rbase + 8) * PSTR + nt * 8 + 2 * tig) = pb;
        }
        __syncwarp();

        #pragma unroll
        for (int ki = 0; ki < 16; ki++) {
            uint32_t a0 = *(const uint32_t*)(Ps + (rbase    ) * PSTR + ki * 8 + tig);
            uint32_t a1 = *(const uint32_t*)(Ps + (rbase + 8) * PSTR + ki * 8 + tig);
            uint32_t a2 = *(const uint32_t*)(Ps + (rbase    ) * PSTR + ki * 8 + tig + 4);
            uint32_t a3 = *(const uint32_t*)(Ps + (rbase + 8) * PSTR + ki * 8 + tig + 4);
            #pragma unroll
            for (int nt = 0; nt < 8; nt++) {
                uint32_t b0 = *(const uint32_t*)(Vs + (ki * 8 + tig    ) * VSTR + nt * 8 + gid);
                uint32_t b1 = *(const uint32_t*)(Vs + (ki * 8 + tig + 4) * VSTR + nt * 8 + gid);
                asm volatile(
                    "mma.sync.aligned.m16n8k8.row.col.f32.tf32.tf32.f32 "
                    "{%0,%1,%2,%3}, {%4,%5,%6,%7}, {%8,%9}, {%0,%1,%2,%3};\n"
                    : "+f"(accO[nt][0]), "+f"(accO[nt][1]),
                      "+f"(accO[nt][2]), "+f"(accO[nt][3])
                    : "r"(a0), "r"(a1), "r"(a2), "r"(a3), "r"(b0), "r"(b1));
            }
        }
    }

    float inv0 = 1.0f / l0, inv1 = 1.0f / l1;
    #pragma unroll
    for (int nt = 0; nt < 8; nt++) {
        int col = nt * 8 + 2 * tig;
        float2 o0, o1;
        o0.x = accO[nt][0] * inv0; o0.y = accO[nt][1] * inv0;
        o1.x = accO[nt][2] * inv1; o1.y = accO[nt][3] * inv1;
        *(float2*)(O + base + (size_t)(qt * 128 + rbase    ) * E_DIM + col) = o0;
        *(float2*)(O + base + (size_t)(qt * 128 + rbase + 8) * E_DIM + col) = o1;
    }
}

// ---------------------------------------------------------------------------
// Residual add + LayerNorm
// ---------------------------------------------------------------------------
__global__ __launch_bounds__(256)
void add_ln_kernel(const float* __restrict__ a, const float* __restrict__ b,
                   const float* __restrict__ g, const float* __restrict__ beta,
                   float* __restrict__ out)
{
    __shared__ float sred[256];
    int row = blockIdx.x;
    int tid = threadIdx.x;
    const float* ar = a + (size_t)row * E_DIM;
    const float* br = b + (size_t)row * E_DIM;
    float* orow = out + (size_t)row * E_DIM;

    float xv[4];
    float lsum = 0.0f;
    #pragma unroll
    for (int j = 0; j < 4; j++) {
        int e = tid + j * 256;
        xv[j] = ar[e] + br[e];
        lsum += xv[j];
    }
    sred[tid] = lsum;
    __syncthreads();
    #pragma unroll
    for (int s = 128; s > 0; s >>= 1) {
        if (tid < s) sred[tid] += sred[tid + s];
        __syncthreads();
    }
    float mean = sred[0] * (1.0f / E_DIM);
    __syncthreads();

    float lvar = 0.0f;
    #pragma unroll
    for (int j = 0; j < 4; j++) {
        float d = xv[j] - mean;
        lvar += d * d;
    }
    sred[tid] = lvar;
    __syncthreads();
    #pragma unroll
    for (int s = 128; s > 0; s >>= 1) {
        if (tid < s) sred[tid] += sred[tid + s];
        __syncthreads();
    }
    float rstd = rsqrtf(sred[0] * (1.0f / E_DIM) + 1e-5f);

    #pragma unroll
    for (int j = 0; j < 4; j++) {
        int e = tid + j * 256;
        orow[e] = (xv[j] - mean) * rstd * g[e] + beta[e];
    }
}

// ---------------------------------------------------------------------------
// Launch
// ---------------------------------------------------------------------------
static void run_gemm(const float* A, const float* W, const float* bias, float* C,
                     __half* wt, int Nd, int Kd, int relu)
{
    transpose_half<<<dim3(Nd / 32, Kd / 32), dim3(32, 8)>>>(W, wt, Kd, Nd);
    dim3 grid(Nd / GBN, M_TOK / GBM);
    if (relu)
        hgemm_bias<1><<<grid, 256, GEMM_SMEM>>>(A, wt, bias, C, Nd, Kd);
    else
        hgemm_bias<0><<<grid, 256, GEMM_SMEM>>>(A, wt, bias, C, Nd, Kd);
}

extern "C" void kernel_launch(void* const* d_in, const int* in_sizes, int n_in,
                              void* d_out, int out_size)
{
    const int*   x    = (const int*)  d_in[0];
    const float* emb  = (const float*)d_in[1];
    const float* Wq   = (const float*)d_in[2];
    const float* bq   = (const float*)d_in[3];
    const float* Wk   = (const float*)d_in[4];
    const float* bk   = (const float*)d_in[5];
    const float* Wv   = (const float*)d_in[6];
    const float* bv   = (const float*)d_in[7];
    const float* Wo   = (const float*)d_in[8];
    const float* bo   = (const float*)d_in[9];
    const float* ln1g = (const float*)d_in[10];
    const float* ln1b = (const float*)d_in[11];
    const float* ln2g = (const float*)d_in[12];
    const float* ln2b = (const float*)d_in[13];
    const float* W1   = (const float*)d_in[14];
    const float* b1   = (const float*)d_in[15];
    const float* W2   = (const float*)d_in[16];
    const float* b2   = (const float*)d_in[17];
    const float* Wout = (const float*)d_in[18];
    const float* bout = (const float*)d_in[19];
    float* out = (float*)d_out;

    float *act, *q, *k, *v, *attn, *tmp, *hbuf, *ff;
    __half* wt;
    cudaGetSymbolAddress((void**)&act,  g_act);
    cudaGetSymbolAddress((void**)&q,    g_q);
    cudaGetSymbolAddress((void**)&k,    g_k);
    cudaGetSymbolAddress((void**)&v,    g_v);
    cudaGetSymbolAddress((void**)&attn, g_attn);
    cudaGetSymbolAddress((void**)&tmp,  g_tmp);
    cudaGetSymbolAddress((void**)&hbuf, g_h);
    cudaGetSymbolAddress((void**)&ff,   g_ff);
    cudaGetSymbolAddress((void**)&wt,   g_wt);

    static int attr_set = 0;
    if (!attr_set) {
        cudaFuncSetAttribute(flash_attn,
                             cudaFuncAttributeMaxDynamicSharedMemorySize, ATTN_SMEM);
        cudaFuncSetAttribute(hgemm_bias<0>,
                             cudaFuncAttributeMaxDynamicSharedMemorySize, GEMM_SMEM);
        cudaFuncSetAttribute(hgemm_bias<1>,
                             cudaFuncAttributeMaxDynamicSharedMemorySize, GEMM_SMEM);
        attr_set = 1;
    }

    embed_kernel<<<M_TOK, 256>>>(x, emb, act);

    for (int i = 0; i < L_NUM; i++) {
        size_t wo = (size_t)i * E_DIM * E_DIM;
        size_t bo_off = (size_t)i * E_DIM;

        run_gemm(act, Wq + wo, bq + bo_off, q, wt, E_DIM, E_DIM, 0);
        run_gemm(act, Wk + wo, bk + bo_off, k, wt, E_DIM, E_DIM, 0);
        run_gemm(act, Wv + wo, bv + bo_off, v, wt, E_DIM, E_DIM, 0);

        flash_attn<<<dim3(S_LEN / 128, H_DIM, N_B), 256, ATTN_SMEM>>>(q, k, v, attn);

        run_gemm(attn, Wo + wo, bo + bo_off, tmp, wt, E_DIM, E_DIM, 0);

        add_ln_kernel<<<M_TOK, 256>>>(tmp, act, ln1g + bo_off, ln1b + bo_off, hbuf);

        run_gemm(hbuf, W1 + (size_t)i * E_DIM * FF_DIM, b1 + (size_t)i * FF_DIM,
                 ff, wt, FF_DIM, E_DIM, 1);
        run_gemm(ff, W2 + (size_t)i * FF_DIM * E_DIM, b2 + bo_off,
                 tmp, wt, E_DIM, FF_DIM, 0);

        add_ln_kernel<<<M_TOK, 256>>>(tmp, hbuf, ln2g + bo_off, ln2b + bo_off, act);
    }

    run_gemm(act, Wout, bout, out, wt, V_DIM, E_DIM, 0);
}

// round 7
// speedup vs baseline: 8.0099x; 1.0199x over previous
#include <cuda_runtime.h>
#include <cuda_fp16.h>
#include <math.h>
#include <stdint.h>

#define E_DIM 1024
#define H_DIM 16
#define D_DIM 64
#define S_LEN 1024
#define N_B   4
#define L_NUM 4
#define FF_DIM 4096
#define V_DIM 32000
#define M_TOK (N_B * S_LEN)   // 4096 token rows
#define QKV_STR (3 * E_DIM)   // 3072

// ---------------------------------------------------------------------------
// Transposed-weight half buffer layout (element offsets)
// ---------------------------------------------------------------------------
#define QKV_LSTR   (3 * E_DIM * E_DIM)            // 3145728 per layer
#define OFF_WO     (L_NUM * QKV_LSTR)             // 12582912
#define WO_LSTR    (E_DIM * E_DIM)                // 1048576
#define OFF_W1     (OFF_WO + L_NUM * WO_LSTR)     // 16777216
#define W1_LSTR    (E_DIM * FF_DIM)               // 4194304
#define OFF_W2     (OFF_W1 + L_NUM * W1_LSTR)     // 33554432
#define W2_LSTR    (FF_DIM * E_DIM)               // 4194304
#define OFF_WOUT   (OFF_W2 + L_NUM * W2_LSTR)     // 50331648
#define WH_TOTAL   (OFF_WOUT + (size_t)V_DIM * E_DIM)  // 83099648 halfs

// ---------------------------------------------------------------------------
// Scratch (device globals; no allocations allowed)
// ---------------------------------------------------------------------------
__device__ float g_act [M_TOK * E_DIM];
__device__ float g_qkv [M_TOK * QKV_STR];
__device__ float g_attn[M_TOK * E_DIM];
__device__ float g_tmp [M_TOK * E_DIM];
__device__ float g_h   [M_TOK * E_DIM];
__device__ float g_ff  [M_TOK * FF_DIM];
__device__ float g_bqkv[L_NUM * QKV_STR];
__device__ __half g_wh [WH_TOTAL];

__device__ __forceinline__ uint32_t f2tf32(float x) {
    uint32_t r;
    asm("cvt.rna.tf32.f32 %0, %1;" : "=r"(r) : "f"(x));
    return r;
}

__device__ __forceinline__ uint32_t smem_u32(const void* p) {
    uint32_t a;
    asm("{ .reg .u64 t; cvta.to.shared.u64 t, %1; cvt.u32.u64 %0, t; }"
        : "=r"(a) : "l"(p));
    return a;
}

__device__ __forceinline__ void ldsm_x4(uint32_t* r, uint32_t addr) {
    asm volatile("ldmatrix.sync.aligned.m8n8.x4.shared.b16 {%0,%1,%2,%3}, [%4];"
                 : "=r"(r[0]), "=r"(r[1]), "=r"(r[2]), "=r"(r[3]) : "r"(addr));
}
__device__ __forceinline__ void ldsm_x2(uint32_t* r, uint32_t addr) {
    asm volatile("ldmatrix.sync.aligned.m8n8.x2.shared.b16 {%0,%1}, [%2];"
                 : "=r"(r[0]), "=r"(r[1]) : "r"(addr));
}

// ---------------------------------------------------------------------------
// Embedding + sinusoidal positional encoding
// ---------------------------------------------------------------------------
__global__ void embed_kernel(const int* __restrict__ x,
                             const float* __restrict__ emb,
                             float* __restrict__ out)
{
    int row = blockIdx.x;
    int s   = row & (S_LEN - 1);
    int tok = x[row];
    const float* erow = emb + (size_t)tok * E_DIM;
    float* orow = out + (size_t)row * E_DIM;

    int e0 = threadIdx.x * 4;
    #pragma unroll
    for (int j = 0; j < 4; j++) {
        int e = e0 + j;
        int even = e & ~1;
        float expo = (float)even / (float)E_DIM;
        float denom = powf(10000.0f, expo);
        float ang = (float)s / denom;
        float pe = (e & 1) ? cosf(ang) : sinf(ang);
        orow[e] = erow[e] + pe;
    }
}

// ---------------------------------------------------------------------------
// Batched transpose+half: Dz[n][k] = half(Wz[k][n]); z = blockIdx.z slice.
// ---------------------------------------------------------------------------
__global__ __launch_bounds__(256)
void transpose_half_b(const float* __restrict__ W, __half* __restrict__ dst,
                      int Kd, int Nd, size_t src_stride, size_t dst_stride)
{
    __shared__ float tile[32][33];
    const float* Wz = W + (size_t)blockIdx.z * src_stride;
    __half* Dz = dst + (size_t)blockIdx.z * dst_stride;
    int n0 = blockIdx.x * 32, k0 = blockIdx.y * 32;
    int tx = threadIdx.x, ty = threadIdx.y;
    #pragma unroll
    for (int dy = 0; dy < 32; dy += 8)
        tile[ty + dy][tx] = Wz[(size_t)(k0 + ty + dy) * Nd + n0 + tx];
    __syncthreads();
    #pragma unroll
    for (int dy = 0; dy < 32; dy += 8)
        Dz[(size_t)(n0 + ty + dy) * Kd + k0 + tx] =
            __float2half_rn(tile[tx][ty + dy]);
}

// ---------------------------------------------------------------------------
// Pack QKV biases: out[l][c] = {bq|bk|bv}[l][c % 1024]
// ---------------------------------------------------------------------------
__global__ void pack_qkv_bias(const float* __restrict__ bq,
                              const float* __restrict__ bk,
                              const float* __restrict__ bv,
                              float* __restrict__ out)
{
    int i = blockIdx.x * 256 + threadIdx.x;      // L*3072 total
    int layer = i / QKV_STR, c = i % QKV_STR;
    float v;
    if (c < E_DIM)           v = bq[layer * E_DIM + c];
    else if (c < 2 * E_DIM)  v = bk[layer * E_DIM + c - E_DIM];
    else                     v = bv[layer * E_DIM + c - 2 * E_DIM];
    out[i] = v;
}

// ---------------------------------------------------------------------------
// FP16 tensor-core GEMM via mma.sync m16n8k16 + ldmatrix (round-6 core).
// C[M,N] = A[M,K](f32) @ Bt[N,K](half)^T + bias, optional ReLU. f32 accum.
// ---------------------------------------------------------------------------
#define GBM 128
#define GBN 128
#define GBK 32
#define ROWB 112
#define A_ST (128 * ROWB)
#define STAGE (2 * A_ST)
#define GEMM_SMEM (2 * STAGE)

template<int RELU>
__global__ __launch_bounds__(256, 2)
void hgemm_bias(const float* __restrict__ A, const __half* __restrict__ Bt,
                const float* __restrict__ bias, float* __restrict__ C,
                int Nd, int Kd)
{
    extern __shared__ char smem[];
    const uint32_t sbase = smem_u32(smem);

    const int tid  = threadIdx.x;
    const int lane = tid & 31;
    const int wid  = tid >> 5;
    const int gid  = lane >> 2;
    const int tig  = lane & 3;

    const int m0 = blockIdx.y * GBM;
    const int n0 = blockIdx.x * GBN;
    const int wm = (wid >> 2) * 64;
    const int wn = (wid & 3) * 32;

    const int arow = wm + (lane & 15);
    const int akoh = (lane & 16) ? 8 : 0;
    const int brow = wn + (lane & 7);
    const int bkoh = (lane & 8) ? 8 : 0;

    const int a_m  = tid >> 3;
    const int a_kc = tid & 7;
    const int b_n  = tid >> 2;
    const int b_kq = tid & 3;

    float acc[4][4][4];
    #pragma unroll
    for (int i = 0; i < 4; i++)
        #pragma unroll
        for (int j = 0; j < 4; j++)
            #pragma unroll
            for (int r = 0; r < 4; r++) acc[i][j][r] = 0.0f;

    const int nK = Kd / GBK;

    {
        #pragma unroll
        for (int p = 0; p < 2; p++) {
            int n = b_n + p * 64;
            uint32_t dst = sbase + A_ST + n * ROWB + b_kq * 16;
            const __half* src = Bt + (size_t)(n0 + n) * Kd + b_kq * 8;
            asm volatile("cp.async.cg.shared.global [%0], [%1], 16;\n"
                         :: "r"(dst), "l"(src));
        }
        asm volatile("cp.async.commit_group;\n");
        #pragma unroll
        for (int p = 0; p < 4; p++) {
            int m = a_m + p * 32;
            float4 v = *(const float4*)(A + (size_t)(m0 + m) * Kd + a_kc * 4);
            __half2 h0 = __floats2half2_rn(v.x, v.y);
            __half2 h1 = __floats2half2_rn(v.z, v.w);
            uint2 u = { *(uint32_t*)&h0, *(uint32_t*)&h1 };
            *(uint2*)(smem + m * ROWB + a_kc * 8) = u;
        }
        asm volatile("cp.async.wait_group 0;\n");
        __syncthreads();
    }

    for (int t = 0; t < nK; t++) {
        const int cur = t & 1;
        const int nxt = cur ^ 1;
        const bool has_next = (t + 1 < nK);

        float4 areg[4];
        if (has_next) {
            #pragma unroll
            for (int p = 0; p < 2; p++) {
                int n = b_n + p * 64;
                uint32_t dst = sbase + nxt * STAGE + A_ST + n * ROWB + b_kq * 16;
                const __half* src = Bt + (size_t)(n0 + n) * Kd + (t + 1) * GBK + b_kq * 8;
                asm volatile("cp.async.cg.shared.global [%0], [%1], 16;\n"
                             :: "r"(dst), "l"(src));
            }
            asm volatile("cp.async.commit_group;\n");
            #pragma unroll
            for (int p = 0; p < 4; p++) {
                int m = a_m + p * 32;
                areg[p] = *(const float4*)(A + (size_t)(m0 + m) * Kd + (t + 1) * GBK + a_kc * 4);
            }
        }

        const uint32_t sA = sbase + cur * STAGE;
        const uint32_t sB = sA + A_ST;
        #pragma unroll
        for (int ko = 0; ko < 32; ko += 16) {
            uint32_t af[4][4], bf[4][2];
            #pragma unroll
            for (int mt = 0; mt < 4; mt++)
                ldsm_x4(af[mt], sA + (arow + mt * 16) * ROWB + (ko + akoh) * 2);
            #pragma unroll
            for (int nt = 0; nt < 4; nt++)
                ldsm_x2(bf[nt], sB + (brow + nt * 8) * ROWB + (ko + bkoh) * 2);
            #pragma unroll
            for (int mt = 0; mt < 4; mt++)
                #pragma unroll
                for (int nt = 0; nt < 4; nt++) {
                    asm volatile(
                        "mma.sync.aligned.m16n8k16.row.col.f32.f16.f16.f32 "
                        "{%0,%1,%2,%3}, {%4,%5,%6,%7}, {%8,%9}, {%0,%1,%2,%3};\n"
                        : "+f"(acc[mt][nt][0]), "+f"(acc[mt][nt][1]),
                          "+f"(acc[mt][nt][2]), "+f"(acc[mt][nt][3])
                        : "r"(af[mt][0]), "r"(af[mt][1]),
                          "r"(af[mt][2]), "r"(af[mt][3]),
                          "r"(bf[nt][0]), "r"(bf[nt][1]));
                }
        }

        if (has_next) {
            char* dstA = smem + nxt * STAGE;
            #pragma unroll
            for (int p = 0; p < 4; p++) {
                int m = a_m + p * 32;
                __half2 h0 = __floats2half2_rn(areg[p].x, areg[p].y);
                __half2 h1 = __floats2half2_rn(areg[p].z, areg[p].w);
                uint2 u = { *(uint32_t*)&h0, *(uint32_t*)&h1 };
                *(uint2*)(dstA + m * ROWB + a_kc * 8) = u;
            }
            asm volatile("cp.async.wait_group 0;\n");
        }
        __syncthreads();
    }

    #pragma unroll
    for (int nt = 0; nt < 4; nt++) {
        int col = n0 + wn + nt * 8 + 2 * tig;
        float b0 = bias[col];
        float b1 = bias[col + 1];
        #pragma unroll
        for (int mt = 0; mt < 4; mt++) {
            int row = m0 + wm + mt * 16 + gid;
            float2 v0, v1;
            v0.x = acc[mt][nt][0] + b0;
            v0.y = acc[mt][nt][1] + b1;
            v1.x = acc[mt][nt][2] + b0;
            v1.y = acc[mt][nt][3] + b1;
            if (RELU) {
                v0.x = fmaxf(v0.x, 0.0f); v0.y = fmaxf(v0.y, 0.0f);
                v1.x = fmaxf(v1.x, 0.0f); v1.y = fmaxf(v1.y, 0.0f);
            }
            *(float2*)(C + (size_t)row * Nd + col)       = v0;
            *(float2*)(C + (size_t)(row + 8) * Nd + col) = v1;
        }
    }
}

// ---------------------------------------------------------------------------
// Flash attention (tf32 mma.sync); reads fused QKV buffer (row stride 3072).
// ---------------------------------------------------------------------------
#define QSTR 68
#define KSTR 68
#define VSTR 72
#define PSTR 132
#define ATTN_SMEM ((128*QSTR + 128*KSTR + 128*VSTR + 128*PSTR) * 4)

__global__ __launch_bounds__(256)
void flash_attn(const float* __restrict__ QKV, float* __restrict__ O)
{
    extern __shared__ float sm[];
    float* Qs = sm;
    float* Ks = Qs + 128 * QSTR;
    float* Vs = Ks + 128 * KSTR;
    float* Ps = Vs + 128 * VSTR;

    const int tid  = threadIdx.x;
    const int lane = tid & 31;
    const int wid  = tid >> 5;
    const int gid  = lane >> 2;
    const int tig  = lane & 3;

    const int qt = gridDim.x - 1 - blockIdx.x;
    const int h  = blockIdx.y;
    const int n  = blockIdx.z;
    const size_t binq = ((size_t)n * S_LEN) * QKV_STR + h * D_DIM;
    const size_t bink = binq + E_DIM;
    const size_t binv = binq + 2 * E_DIM;
    const size_t bout = ((size_t)n * S_LEN) * E_DIM + h * D_DIM;
    const float scale = 1.0f / 32.0f;
    const int wrow = wid * 16;

    #pragma unroll
    for (int l = 0; l < 8; l++) {
        int idx = tid + l * 256;
        int r = idx >> 4, c4 = (idx & 15) * 4;
        float4 v = *(const float4*)(QKV + binq + (size_t)(qt * 128 + r) * QKV_STR + c4);
        uint4 u;
        u.x = f2tf32(v.x * scale); u.y = f2tf32(v.y * scale);
        u.z = f2tf32(v.z * scale); u.w = f2tf32(v.w * scale);
        *(uint4*)(Qs + r * QSTR + c4) = u;
    }

    float accO[8][4];
    #pragma unroll
    for (int i = 0; i < 8; i++)
        #pragma unroll
        for (int j = 0; j < 4; j++) accO[i][j] = 0.0f;
    float m0 = -1e30f, m1 = -1e30f, l0 = 0.0f, l1 = 0.0f;

    const int rbase = wrow + gid;

    for (int kt = 0; kt <= qt; kt++) {
        __syncthreads();
        #pragma unroll
        for (int l = 0; l < 8; l++) {
            int idx = tid + l * 256;
            int r = idx >> 4, c4 = (idx & 15) * 4;
            const size_t roff = (size_t)(kt * 128 + r) * QKV_STR + c4;
            float4 kv = *(const float4*)(QKV + bink + roff);
            uint4 ku;
            ku.x = f2tf32(kv.x); ku.y = f2tf32(kv.y);
            ku.z = f2tf32(kv.z); ku.w = f2tf32(kv.w);
            *(uint4*)(Ks + r * KSTR + c4) = ku;
            float4 vv = *(const float4*)(QKV + binv + roff);
            uint4 vu;
            vu.x = f2tf32(vv.x); vu.y = f2tf32(vv.y);
            vu.z = f2tf32(vv.z); vu.w = f2tf32(vv.w);
            *(uint4*)(Vs + r * VSTR + c4) = vu;
        }
        __syncthreads();

        float accS[16][4];
        #pragma unroll
        for (int i = 0; i < 16; i++)
            #pragma unroll
            for (int j = 0; j < 4; j++) accS[i][j] = 0.0f;

        #pragma unroll
        for (int ks = 0; ks < 8; ks++) {
            uint32_t a0 = *(const uint32_t*)(Qs + (rbase    ) * QSTR + ks * 8 + tig);
            uint32_t a1 = *(const uint32_t*)(Qs + (rbase + 8) * QSTR + ks * 8 + tig);
            uint32_t a2 = *(const uint32_t*)(Qs + (rbase    ) * QSTR + ks * 8 + tig + 4);
            uint32_t a3 = *(const uint32_t*)(Qs + (rbase + 8) * QSTR + ks * 8 + tig + 4);
            #pragma unroll
            for (int nt = 0; nt < 16; nt++) {
                uint32_t b0 = *(const uint32_t*)(Ks + (nt * 8 + gid) * KSTR + ks * 8 + tig);
                uint32_t b1 = *(const uint32_t*)(Ks + (nt * 8 + gid) * KSTR + ks * 8 + tig + 4);
                asm volatile(
                    "mma.sync.aligned.m16n8k8.row.col.f32.tf32.tf32.f32 "
                    "{%0,%1,%2,%3}, {%4,%5,%6,%7}, {%8,%9}, {%0,%1,%2,%3};\n"
                    : "+f"(accS[nt][0]), "+f"(accS[nt][1]),
                      "+f"(accS[nt][2]), "+f"(accS[nt][3])
                    : "r"(a0), "r"(a1), "r"(a2), "r"(a3), "r"(b0), "r"(b1));
            }
        }

        if (kt == qt) {
            #pragma unroll
            for (int nt = 0; nt < 16; nt++) {
                int c = nt * 8 + 2 * tig;
                if (c     > rbase    ) accS[nt][0] = -1e30f;
                if (c + 1 > rbase    ) accS[nt][1] = -1e30f;
                if (c     > rbase + 8) accS[nt][2] = -1e30f;
                if (c + 1 > rbase + 8) accS[nt][3] = -1e30f;
            }
        }

        float mx0 = -1e30f, mx1 = -1e30f;
        #pragma unroll
        for (int nt = 0; nt < 16; nt++) {
            mx0 = fmaxf(mx0, fmaxf(accS[nt][0], accS[nt][1]));
            mx1 = fmaxf(mx1, fmaxf(accS[nt][2], accS[nt][3]));
        }
        mx0 = fmaxf(mx0, __shfl_xor_sync(0xffffffffu, mx0, 1));
        mx0 = fmaxf(mx0, __shfl_xor_sync(0xffffffffu, mx0, 2));
        mx1 = fmaxf(mx1, __shfl_xor_sync(0xffffffffu, mx1, 1));
        mx1 = fmaxf(mx1, __shfl_xor_sync(0xffffffffu, mx1, 2));

        float mn0 = fmaxf(m0, mx0), mn1 = fmaxf(m1, mx1);
        float al0 = __expf(m0 - mn0), al1 = __expf(m1 - mn1);
        m0 = mn0; m1 = mn1;

        float s0 = 0.0f, s1 = 0.0f;
        #pragma unroll
        for (int nt = 0; nt < 16; nt++) {
            float p0 = __expf(accS[nt][0] - mn0);
            float p1 = __expf(accS[nt][1] - mn0);
            float p2 = __expf(accS[nt][2] - mn1);
            float p3 = __expf(accS[nt][3] - mn1);
            accS[nt][0] = p0; accS[nt][1] = p1;
            accS[nt][2] = p2; accS[nt][3] = p3;
            s0 += p0 + p1; s1 += p2 + p3;
        }
        s0 += __shfl_xor_sync(0xffffffffu, s0, 1);
        s0 += __shfl_xor_sync(0xffffffffu, s0, 2);
        s1 += __shfl_xor_sync(0xffffffffu, s1, 1);
        s1 += __shfl_xor_sync(0xffffffffu, s1, 2);
        l0 = l0 * al0 + s0;
        l1 = l1 * al1 + s1;

        #pragma unroll
        for (int i = 0; i < 8; i++) {
            accO[i][0] *= al0; accO[i][1] *= al0;
            accO[i][2] *= al1; accO[i][3] *= al1;
        }

        #pragma unroll
        for (int nt = 0; nt < 16; nt++) {
            uint2 pa, pb;
            pa.x = f2tf32(accS[nt][0]); pa.y = f2tf32(accS[nt][1]);
            pb.x = f2tf32(accS[nt][2]); pb.y = f2tf32(accS[nt][3]);
            *(uint2*)(Ps + (rbase    ) * PSTR + nt * 8 + 2 * tig) = pa;
            *(uint2*)(Ps + (rbase + 8) * PSTR + nt * 8 + 2 * tig) = pb;
        }
        __syncwarp();

        #pragma unroll
        for (int ki = 0; ki < 16; ki++) {
            uint32_t a0 = *(const uint32_t*)(Ps + (rbase    ) * PSTR + ki * 8 + tig);
            uint32_t a1 = *(const uint32_t*)(Ps + (rbase + 8) * PSTR + ki * 8 + tig);
            uint32_t a2 = *(const uint32_t*)(Ps + (rbase    ) * PSTR + ki * 8 + tig + 4);
            uint32_t a3 = *(const uint32_t*)(Ps + (rbase + 8) * PSTR + ki * 8 + tig + 4);
            #pragma unroll
            for (int nt = 0; nt < 8; nt++) {
                uint32_t b0 = *(const uint32_t*)(Vs + (ki * 8 + tig    ) * VSTR + nt * 8 + gid);
                uint32_t b1 = *(const uint32_t*)(Vs + (ki * 8 + tig + 4) * VSTR + nt * 8 + gid);
                asm volatile(
                    "mma.sync.aligned.m16n8k8.row.col.f32.tf32.tf32.f32 "
                    "{%0,%1,%2,%3}, {%4,%5,%6,%7}, {%8,%9}, {%0,%1,%2,%3};\n"
                    : "+f"(accO[nt][0]), "+f"(accO[nt][1]),
                      "+f"(accO[nt][2]), "+f"(accO[nt][3])
                    : "r"(a0), "r"(a1), "r"(a2), "r"(a3), "r"(b0), "r"(b1));
            }
        }
    }

    float inv0 = 1.0f / l0, inv1 = 1.0f / l1;
    #pragma unroll
    for (int nt = 0; nt < 8; nt++) {
        int col = nt * 8 + 2 * tig;
        float2 o0, o1;
        o0.x = accO[nt][0] * inv0; o0.y = accO[nt][1] * inv0;
        o1.x = accO[nt][2] * inv1; o1.y = accO[nt][3] * inv1;
        *(float2*)(O + bout + (size_t)(qt * 128 + rbase    ) * E_DIM + col) = o0;
        *(float2*)(O + bout + (size_t)(qt * 128 + rbase + 8) * E_DIM + col) = o1;
    }
}

// ---------------------------------------------------------------------------
// Residual add + LayerNorm
// ---------------------------------------------------------------------------
__global__ __launch_bounds__(256)
void add_ln_kernel(const float* __restrict__ a, const float* __restrict__ b,
                   const float* __restrict__ g, const float* __restrict__ beta,
                   float* __restrict__ out)
{
    __shared__ float sred[256];
    int row = blockIdx.x;
    int tid = threadIdx.x;
    const float* ar = a + (size_t)row * E_DIM;
    const float* br = b + (size_t)row * E_DIM;
    float* orow = out + (size_t)row * E_DIM;

    float xv[4];
    float lsum = 0.0f;
    #pragma unroll
    for (int j = 0; j < 4; j++) {
        int e = tid + j * 256;
        xv[j] = ar[e] + br[e];
        lsum += xv[j];
    }
    sred[tid] = lsum;
    __syncthreads();
    #pragma unroll
    for (int s = 128; s > 0; s >>= 1) {
        if (tid < s) sred[tid] += sred[tid + s];
        __syncthreads();
    }
    float mean = sred[0] * (1.0f / E_DIM);
    __syncthreads();

    float lvar = 0.0f;
    #pragma unroll
    for (int j = 0; j < 4; j++) {
        float d = xv[j] - mean;
        lvar += d * d;
    }
    sred[tid] = lvar;
    __syncthreads();
    #pragma unroll
    for (int s = 128; s > 0; s >>= 1) {
        if (tid < s) sred[tid] += sred[tid + s];
        __syncthreads();
    }
    float rstd = rsqrtf(sred[0] * (1.0f / E_DIM) + 1e-5f);

    #pragma unroll
    for (int j = 0; j < 4; j++) {
        int e = tid + j * 256;
        orow[e] = (xv[j] - mean) * rstd * g[e] + beta[e];
    }
}

// ---------------------------------------------------------------------------
// Launch
// ---------------------------------------------------------------------------
static void launch_hgemm(const float* A, const __half* Bt, const float* bias,
                         float* C, int Nd, int Kd, int relu)
{
    dim3 grid(Nd / GBN, M_TOK / GBM);
    if (relu)
        hgemm_bias<1><<<grid, 256, GEMM_SMEM>>>(A, Bt, bias, C, Nd, Kd);
    else
        hgemm_bias<0><<<grid, 256, GEMM_SMEM>>>(A, Bt, bias, C, Nd, Kd);
}

extern "C" void kernel_launch(void* const* d_in, const int* in_sizes, int n_in,
                              void* d_out, int out_size)
{
    const int*   x    = (const int*)  d_in[0];
    const float* emb  = (const float*)d_in[1];
    const float* Wq   = (const float*)d_in[2];
    const float* bq   = (const float*)d_in[3];
    const float* Wk   = (const float*)d_in[4];
    const float* bk   = (const float*)d_in[5];
    const float* Wv   = (const float*)d_in[6];
    const float* bv   = (const float*)d_in[7];
    const float* Wo   = (const float*)d_in[8];
    const float* bo   = (const float*)d_in[9];
    const float* ln1g = (const float*)d_in[10];
    const float* ln1b = (const float*)d_in[11];
    const float* ln2g = (const float*)d_in[12];
    const float* ln2b = (const float*)d_in[13];
    const float* W1   = (const float*)d_in[14];
    const float* b1   = (const float*)d_in[15];
    const float* W2   = (const float*)d_in[16];
    const float* b2   = (const float*)d_in[17];
    const float* Wout = (const float*)d_in[18];
    const float* bout = (const float*)d_in[19];
    float* out = (float*)d_out;

    float *act, *qkv, *attn, *tmp, *hbuf, *ff, *bqkv;
    __half* wh;
    cudaGetSymbolAddress((void**)&act,  g_act);
    cudaGetSymbolAddress((void**)&qkv,  g_qkv);
    cudaGetSymbolAddress((void**)&attn, g_attn);
    cudaGetSymbolAddress((void**)&tmp,  g_tmp);
    cudaGetSymbolAddress((void**)&hbuf, g_h);
    cudaGetSymbolAddress((void**)&ff,   g_ff);
    cudaGetSymbolAddress((void**)&bqkv, g_bqkv);
    cudaGetSymbolAddress((void**)&wh,   g_wh);

    static int attr_set = 0;
    if (!attr_set) {
        cudaFuncSetAttribute(flash_attn,
                             cudaFuncAttributeMaxDynamicSharedMemorySize, ATTN_SMEM);
        cudaFuncSetAttribute(hgemm_bias<0>,
                             cudaFuncAttributeMaxDynamicSharedMemorySize, GEMM_SMEM);
        cudaFuncSetAttribute(hgemm_bias<1>,
                             cudaFuncAttributeMaxDynamicSharedMemorySize, GEMM_SMEM);
        attr_set = 1;
    }

    // ---- upfront: all weight transposes (batched over layers) + bias pack ----
    {
        dim3 blk(32, 8);
        dim3 gEE(E_DIM / 32, E_DIM / 32, L_NUM);
        transpose_half_b<<<gEE, blk>>>(Wq, wh + 0 * WO_LSTR, E_DIM, E_DIM,
                                       (size_t)E_DIM * E_DIM, QKV_LSTR);
        transpose_half_b<<<gEE, blk>>>(Wk, wh + 1 * WO_LSTR, E_DIM, E_DIM,
                                       (size_t)E_DIM * E_DIM, QKV_LSTR);
        transpose_half_b<<<gEE, blk>>>(Wv, wh + 2 * WO_LSTR, E_DIM, E_DIM,
                                       (size_t)E_DIM * E_DIM, QKV_LSTR);
        transpose_half_b<<<gEE, blk>>>(Wo, wh + OFF_WO, E_DIM, E_DIM,
                                       (size_t)E_DIM * E_DIM, WO_LSTR);
        dim3 gW1(FF_DIM / 32, E_DIM / 32, L_NUM);
        transpose_half_b<<<gW1, blk>>>(W1, wh + OFF_W1, E_DIM, FF_DIM,
                                       (size_t)E_DIM * FF_DIM, W1_LSTR);
        dim3 gW2(E_DIM / 32, FF_DIM / 32, L_NUM);
        transpose_half_b<<<gW2, blk>>>(W2, wh + OFF_W2, FF_DIM, E_DIM,
                                       (size_t)FF_DIM * E_DIM, W2_LSTR);
        dim3 gWV(V_DIM / 32, E_DIM / 32, 1);
        transpose_half_b<<<gWV, blk>>>(Wout, wh + OFF_WOUT, E_DIM, V_DIM,
                                       (size_t)E_DIM * V_DIM, 0);
        pack_qkv_bias<<<(L_NUM * QKV_STR) / 256, 256>>>(bq, bk, bv, bqkv);
    }

    embed_kernel<<<M_TOK, 256>>>(x, emb, act);

    for (int i = 0; i < L_NUM; i++) {
        size_t bo_off = (size_t)i * E_DIM;

        launch_hgemm(act, wh + (size_t)i * QKV_LSTR, bqkv + (size_t)i * QKV_STR,
                     qkv, QKV_STR, E_DIM, 0);

        flash_attn<<<dim3(S_LEN / 128, H_DIM, N_B), 256, ATTN_SMEM>>>(qkv, attn);

        launch_hgemm(attn, wh + OFF_WO + (size_t)i * WO_LSTR, bo + bo_off,
                     tmp, E_DIM, E_DIM, 0);

        add_ln_kernel<<<M_TOK, 256>>>(tmp, act, ln1g + bo_off, ln1b + bo_off, hbuf);

        launch_hgemm(hbuf, wh + OFF_W1 + (size_t)i * W1_LSTR, b1 + (size_t)i * FF_DIM,
                     ff, FF_DIM, E_DIM, 1);
        launch_hgemm(ff, wh + OFF_W2 + (size_t)i * W2_LSTR, b2 + bo_off,
                     tmp, E_DIM, FF_DIM, 0);

        add_ln_kernel<<<M_TOK, 256>>>(tmp, hbuf, ln2g + bo_off, ln2b + bo_off, act);
    }

    launch_hgemm(act, wh + OFF_WOUT, bout, out, V_DIM, E_DIM, 0);
}